// round 13
// baseline (speedup 1.0000x reference)
#include <cuda_runtime.h>
#include <cuda_fp16.h>
#include <cstdint>

#define D 128
#define ROWSTRIDE 144
#define NMAX 51200

// ---- precompute kernel smem layout (2 A tiles + 2 W slots) ----
#define P_A0   0
#define P_A1   18432
#define P_W0   36864
#define P_W1   55296
#define P_SMEM 73728

// ---- edge kernel smem layout (2 CTAs/SM) ----
#define WS0   0                            // W slot 0 (128n x 64k, 18432B)
#define WS1   18432                        // W slot 1
#define A0T   36864                        // A/H tile c0 (64 x 144 = 9216)
#define A1T   46080                        // A/H tile c1
#define HE0   55296                        // H-edge c0
#define HE1   64512                        // H-edge c1
#define US0   73728                        // U staging br0 (64 x 272 = 17408)
#define US1   91136                        // U staging br1
#define STG   73728                        // node-out staging (64 x 528) reuses US
#define IDXO  108544                       // sidx[64], ridx[64]
#define BIASO 109056                       // 512 floats
#define E_SMEM 111104
#define USTRIDE 272
#define STAG_STRIDE 528

__device__ __forceinline__ uint32_t smem_u32(const void* p) {
    uint32_t a;
    asm("{ .reg .u64 t; cvta.to.shared.u64 t, %1; cvt.u32.u64 %0, t; }" : "=r"(a) : "l"(p));
    return a;
}
__device__ __forceinline__ float leaky(float x) { return x > 0.0f ? x : 0.01f * x; }
__device__ __forceinline__ uint32_t pack_f16(float a, float b) {
    __half2 t = __floats2half2_rn(a, b);
    return reinterpret_cast<uint32_t&>(t);
}
__device__ __forceinline__ __half2 u2h2(uint32_t u) { return reinterpret_cast<__half2&>(u); }
__device__ __forceinline__ uint32_t h22u(__half2 h) { return reinterpret_cast<uint32_t&>(h); }
__device__ __forceinline__ void ldsm_x4(uint32_t addr, uint32_t r[4]) {
    asm volatile("ldmatrix.sync.aligned.m8n8.x4.shared.b16 {%0,%1,%2,%3}, [%4];"
                 : "=r"(r[0]), "=r"(r[1]), "=r"(r[2]), "=r"(r[3]) : "r"(addr));
}
__device__ __forceinline__ void mma_f16(float* c, const uint32_t* a, uint32_t b0, uint32_t b1) {
    asm volatile("mma.sync.aligned.m16n8k16.row.col.f32.f16.f16.f32 "
                 "{%0,%1,%2,%3}, {%4,%5,%6,%7}, {%8,%9}, {%0,%1,%2,%3};"
                 : "+f"(c[0]), "+f"(c[1]), "+f"(c[2]), "+f"(c[3])
                 : "r"(a[0]), "r"(a[1]), "r"(a[2]), "r"(a[3]), "r"(b0), "r"(b1));
}
__device__ __forceinline__ void cp_async16(uint32_t saddr, const void* gaddr) {
    asm volatile("cp.async.cg.shared.global [%0], [%1], 16;" :: "r"(saddr), "l"(gaddr));
}
#define CP_COMMIT()  asm volatile("cp.async.commit_group;" ::: "memory")
#define CP_WAIT0()   asm volatile("cp.async.wait_group 0;" ::: "memory")
#define FENCE_PROXY_ASYNC() asm volatile("fence.proxy.async.shared::cta;" ::: "memory")

// ============================================================================
// Device scratch
// ============================================================================
__device__ __half g_W0T[2][128 * 384];   // [branch][n(out)][k] transposed fp16
__device__ __half g_W1T[2][128 * 128];
__device__ __half g_Us[NMAX * 256];      // per-node sender partials [n][br*128+c]
__device__ __half g_Ur[NMAX * 256];      // per-node receiver partials
__device__ float g_nsum[256 * 128];      // per-graph node sums
__device__ float g_esum[256 * 128];      // per-graph edge sums
__device__ float g_cat[256][384];        // concat of 3 global-branch MLPs

// ============================================================================
// [0] zero new_nodes
// ============================================================================
__global__ void zero_nodes_kernel(float4* __restrict__ p, int n4) {
    int i = blockIdx.x * 256 + threadIdx.x;
    if (i < n4) p[i] = make_float4(0.f, 0.f, 0.f, 0.f);
}

// ============================================================================
// [1] weight prep: transpose + fp16 convert
// ============================================================================
__global__ void prep_weights(const float* __restrict__ nW0, const float* __restrict__ nW1,
                             const float* __restrict__ eW0, const float* __restrict__ eW1)
{
    int i = blockIdx.x * 256 + threadIdx.x;
    if (i < 98304) {                      // W0T: 2 * 128*384
        int b = i / 49152, r = i % 49152;
        int n = r / 384, k = r % 384;
        g_W0T[b][n * 384 + k] = __float2half_rn((b ? eW0 : nW0)[k * 128 + n]);
    } else if (i < 131072) {              // W1T: 2 * 128*128
        int j = i - 98304;
        int b = j / 16384, r = j % 16384;
        int n = r / 128, k = r % 128;
        g_W1T[b][n * 128 + k] = __float2half_rn((b ? eW1 : nW1)[k * 128 + n]);
    }
}

// ============================================================================
// [2] precompute U_s / U_r + per-graph node sums: grid N/128, 512 thr,
//     2 CTAs/SM (75KB smem). W: 2 slots reloaded per group.
// ============================================================================
__global__ __launch_bounds__(512, 2)
void precompute_u_kernel(const float* __restrict__ nodes, int N, int npg)
{
    extern __shared__ char smem[];
    const uint32_t sb = smem_u32(smem);
    const int tid = threadIdx.x;
    const int wid = tid >> 5;
    const int lane = tid & 31;
    const int wm = wid >> 2, wn = wid & 3;     // 4x4: M=32/warp, N=32/warp
    const int n0 = blockIdx.x * 128;

    // A: nodes rows -> fp16 tiles P_A0/P_A1
    {
        int row = tid >> 2;
        int nn = n0 + row; if (nn >= N) nn = N - 1;
        int cbase = (tid & 3) * 32;
        const float4* p4 = (const float4*)(nodes + (size_t)nn * D + cbase);
        float4 pf[8];
        #pragma unroll
        for (int i = 0; i < 8; i++) pf[i] = p4[i];
        #pragma unroll
        for (int i = 0; i < 8; i++) {
            float4 x = pf[i];
            int c = cbase + i * 4;
            char* A = smem + ((c >> 6) ? P_A1 : P_A0);
            *(uint2*)(A + row * ROWSTRIDE + (c & 63) * 2) =
                make_uint2(pack_f16(x.x, x.y), pack_f16(x.z, x.w));
        }
    }
    __syncthreads();

    // per-graph node column sums (from fp16 A tiles)
    {
        int col = tid & 127, grp = tid >> 7;
        const char* A = smem + ((col >> 6) ? P_A1 : P_A0);
        int cl = col & 63;
        int rbase = grp * 32;
        int gg = (n0 + rbase) / npg;
        int split = (gg + 1) * npg - (n0 + rbase);
        if (split > 32) split = 32;
        float s0 = 0.f, s1 = 0.f;
        #pragma unroll 8
        for (int r = 0; r < 32; r++) {
            int n = n0 + rbase + r;
            if (n < N) {
                float v = __half2float(*(const __half*)(A + (rbase + r) * ROWSTRIDE + cl * 2));
                if (r < split) s0 += v; else s1 += v;
            }
        }
        atomicAdd(&g_nsum[gg * 128 + col], s0);
        if (split < 32 && (n0 + rbase + split) < N)
            atomicAdd(&g_nsum[(gg + 1) * 128 + col], s1);
    }

    #pragma unroll 1
    for (int g = 0; g < 4; g++) {
        int tab = g >> 1, br = g & 1;

        // load both W kc-slots for this group
        #pragma unroll
        for (int u = 0; u < 4; u++) {
            int i = tid + u * 512;
            int t = i >> 10, r = i & 1023, n = r >> 3, q = r & 7;
            cp_async16(sb + P_W0 + t * 18432 + n * ROWSTRIDE + q * 16,
                       (const char*)g_W0T[br] + n * 768 + tab * 256 + t * 128 + q * 16);
        }
        CP_COMMIT();
        CP_WAIT0();
        __syncthreads();

        float acc[2][4][4];
        #pragma unroll
        for (int i = 0; i < 2; i++)
            #pragma unroll
            for (int j = 0; j < 4; j++)
                #pragma unroll
                for (int q = 0; q < 4; q++) acc[i][j][q] = 0.f;

        #pragma unroll
        for (int kc = 0; kc < 2; kc++) {
            uint32_t A = sb + (kc ? P_A1 : P_A0);
            uint32_t W = sb + P_W0 + kc * 18432;
            #pragma unroll
            for (int kk = 0; kk < 4; kk++) {
                uint32_t ah[2][4];
                #pragma unroll
                for (int i = 0; i < 2; i++) {
                    uint32_t off = (wm * 32 + i * 16 + (lane & 15)) * ROWSTRIDE
                                 + (lane >> 4) * 16 + kk * 32;
                    ldsm_x4(A + off, ah[i]);
                }
                uint32_t boffA = (wn * 32 + ((lane >> 4) * 8) + (lane & 7)) * ROWSTRIDE
                               + ((lane >> 3) & 1) * 16 + kk * 32;
                uint32_t bh[2][4];
                ldsm_x4(W + boffA, bh[0]);
                ldsm_x4(W + boffA + 16 * ROWSTRIDE, bh[1]);
                #pragma unroll
                for (int i = 0; i < 2; i++)
                    #pragma unroll
                    for (int j = 0; j < 4; j++)
                        mma_f16(acc[i][j], ah[i], bh[j >> 1][(j & 1) * 2], bh[j >> 1][(j & 1) * 2 + 1]);
            }
        }

        __half* U = tab ? g_Ur : g_Us;
        #pragma unroll
        for (int i = 0; i < 2; i++) {
            int r0 = wm * 32 + i * 16 + (lane >> 2);
            int nA = n0 + r0, nB = nA + 8;
            #pragma unroll
            for (int j = 0; j < 4; j++) {
                int c = wn * 32 + j * 8 + (lane & 3) * 2;
                if (nA < N)
                    *(uint32_t*)(U + (size_t)nA * 256 + br * 128 + c) =
                        pack_f16(acc[i][j][0], acc[i][j][1]);
                if (nB < N)
                    *(uint32_t*)(U + (size_t)nB * 256 + br * 128 + c) =
                        pack_f16(acc[i][j][2], acc[i][j][3]);
            }
        }
        __syncthreads();   // W slots reusable
    }
}

// ============================================================================
// [4] global branch MLPs: grid (G, 3), block 256 (k-split halves) -> g_cat
// ============================================================================
__global__ void global_branch_kernel(const float* __restrict__ globals_,
                                     const float* gW0, const float* gb0, const float* gW1, const float* gb1,
                                     const float* nW0, const float* nb0, const float* nW1, const float* nb1,
                                     const float* eW0, const float* eb0, const float* eW1, const float* eb1)
{
    __shared__ float in[D];
    __shared__ float h[D];
    __shared__ float part[2][D];
    int g = blockIdx.x, b = blockIdx.y;
    int d = threadIdx.x & 127, half = threadIdx.x >> 7;
    int k0 = half * 64;

    const float *W0, *b0, *W1, *b1;
    if (b == 0)      { W0 = gW0; b0 = gb0; W1 = gW1; b1 = gb1;
                       if (!half) in[d] = globals_[(size_t)g * D + d]; }
    else if (b == 1) { W0 = nW0; b0 = nb0; W1 = nW1; b1 = nb1;
                       if (!half) in[d] = g_nsum[g * D + d]; }
    else             { W0 = eW0; b0 = eb0; W1 = eW1; b1 = eb1;
                       if (!half) in[d] = g_esum[g * D + d]; }
    __syncthreads();

    float a0 = 0.f, a1 = 0.f, a2 = 0.f, a3 = 0.f;
    #pragma unroll 4
    for (int k = k0; k < k0 + 64; k += 4) {
        a0 = fmaf(in[k],     __ldg(W0 + k * D + d),       a0);
        a1 = fmaf(in[k + 1], __ldg(W0 + (k + 1) * D + d), a1);
        a2 = fmaf(in[k + 2], __ldg(W0 + (k + 2) * D + d), a2);
        a3 = fmaf(in[k + 3], __ldg(W0 + (k + 3) * D + d), a3);
    }
    part[half][d] = (a0 + a1) + (a2 + a3);
    __syncthreads();
    if (!half) h[d] = leaky(part[0][d] + part[1][d] + __ldg(b0 + d));
    __syncthreads();

    a0 = a1 = a2 = a3 = 0.f;
    #pragma unroll 4
    for (int k = k0; k < k0 + 64; k += 4) {
        a0 = fmaf(h[k],     __ldg(W1 + k * D + d),       a0);
        a1 = fmaf(h[k + 1], __ldg(W1 + (k + 1) * D + d), a1);
        a2 = fmaf(h[k + 2], __ldg(W1 + (k + 2) * D + d), a2);
        a3 = fmaf(h[k + 3], __ldg(W1 + (k + 3) * D + d), a3);
    }
    part[half][d] = (a0 + a1) + (a2 + a3);
    __syncthreads();
    if (!half)
        g_cat[g][b * D + d] = leaky(part[0][d] + part[1][d] + __ldg(b1 + d));
}

// ============================================================================
// [5] final global MLP: grid G, block 256 (k-split halves)
// ============================================================================
__global__ void global_final_kernel(const float* fW0, const float* fb0,
                                    const float* fW1, const float* fb1,
                                    float* __restrict__ out_global)
{
    __shared__ float cat[3 * D];
    __shared__ float h[D];
    __shared__ float part[2][D];
    int g = blockIdx.x;
    int d = threadIdx.x & 127, half = threadIdx.x >> 7;

    if (!half) {
        cat[d]         = g_cat[g][d];
        cat[D + d]     = g_cat[g][D + d];
        cat[2 * D + d] = g_cat[g][2 * D + d];
    }
    __syncthreads();

    float a0 = 0.f, a1 = 0.f, a2 = 0.f, a3 = 0.f;
    int k0 = half * 192;
    #pragma unroll 4
    for (int k = k0; k < k0 + 192; k += 4) {
        a0 = fmaf(cat[k],     __ldg(fW0 + k * D + d),       a0);
        a1 = fmaf(cat[k + 1], __ldg(fW0 + (k + 1) * D + d), a1);
        a2 = fmaf(cat[k + 2], __ldg(fW0 + (k + 2) * D + d), a2);
        a3 = fmaf(cat[k + 3], __ldg(fW0 + (k + 3) * D + d), a3);
    }
    part[half][d] = (a0 + a1) + (a2 + a3);
    __syncthreads();
    if (!half) h[d] = leaky(part[0][d] + part[1][d] + __ldg(fb0 + d));
    __syncthreads();

    a0 = a1 = a2 = a3 = 0.f;
    int k1 = half * 64;
    #pragma unroll 4
    for (int k = k1; k < k1 + 64; k += 4) {
        a0 = fmaf(h[k],     __ldg(fW1 + k * D + d),       a0);
        a1 = fmaf(h[k + 1], __ldg(fW1 + (k + 1) * D + d), a1);
        a2 = fmaf(h[k + 2], __ldg(fW1 + (k + 2) * D + d), a2);
        a3 = fmaf(h[k + 3], __ldg(fW1 + (k + 3) * D + d), a3);
    }
    part[half][d] = (a0 + a1) + (a2 + a3);
    __syncthreads();
    if (!half)
        out_global[(size_t)g * D + d] = leaky(part[0][d] + part[1][d] + __ldg(fb1 + d));
}

// ============================================================================
// [3] main fused edge kernel: M=64 edges/CTA, 256 threads, 2 CTAs/SM.
// ============================================================================
__global__ __launch_bounds__(256, 2)
void edge_mma_kernel(const float* __restrict__ edges,
                     const int*   __restrict__ senders,
                     const int*   __restrict__ receivers,
                     const float* __restrict__ nb0f, const float* __restrict__ nb1f,
                     const float* __restrict__ eb0f, const float* __restrict__ eb1f,
                     float* __restrict__ new_nodes,
                     float* __restrict__ new_edges,
                     int E, int epg)
{
    extern __shared__ char smem[];
    const uint32_t sb = smem_u32(smem);
    const int tid  = threadIdx.x;
    const int wid  = tid >> 5;
    const int lane = tid & 31;
    const int wm   = wid >> 2;   // 0..1 (M offset wm*32)
    const int wn   = wid & 3;    // 0..3 (N offset wn*32)
    const int e0   = blockIdx.x * 64;

    int*   sidx = (int*)(smem + IDXO);
    int*   ridx = (int*)(smem + IDXO + 256);
    float* bias = (float*)(smem + BIASO);

    // cp.async W0e chunk0 -> slots (br0 -> WS0, br1 -> WS1)
    #pragma unroll
    for (int u = 0; u < 8; u++) {
        int i = tid + u * 256;
        int t = i >> 10, r = i & 1023, n = r >> 3, q = r & 7;
        cp_async16(sb + t * 18432 + n * ROWSTRIDE + q * 16,
                   (const char*)g_W0T[t] + n * 768 + 512 + q * 16);
    }
    CP_COMMIT();

    if (tid < 64) {
        int ec = (e0 + tid < E) ? e0 + tid : E - 1;
        sidx[tid] = senders[ec];
        ridx[tid] = receivers[ec];
    }
    if (tid < 128) { bias[tid] = nb0f[tid]; bias[256 + tid] = eb0f[tid]; }
    else { int t = tid - 128; bias[128 + t] = nb1f[t]; bias[384 + t] = eb1f[t]; }

    // stage U branch-0 (indices straight from global; hides behind loads+L1 MMA)
    #pragma unroll
    for (int u = 0; u < 4; u++) {
        int i = tid + u * 256;
        int row = i >> 4, q = i & 15;
        int ec = (e0 + row < E) ? e0 + row : E - 1;
        int s = __ldg(senders + ec);
        int r = __ldg(receivers + ec);
        uint4 a = *(const uint4*)(g_Us + (size_t)s * 256 + q * 8);
        uint4 b = *(const uint4*)(g_Ur + (size_t)r * 256 + q * 8);
        uint4 o;
        o.x = h22u(__hadd2(u2h2(a.x), u2h2(b.x)));
        o.y = h22u(__hadd2(u2h2(a.y), u2h2(b.y)));
        o.z = h22u(__hadd2(u2h2(a.z), u2h2(b.z)));
        o.w = h22u(__hadd2(u2h2(a.w), u2h2(b.w)));
        *(uint4*)(smem + US0 + row * USTRIDE + q * 16) = o;
    }

    // A: edge rows (contiguous) -> fp16 tiles A0/A1
    {
        int row = tid >> 2;
        int ec = (e0 + row < E) ? e0 + row : E - 1;
        int cbase = (tid & 3) * 32;
        const float4* p4 = (const float4*)(edges + (size_t)ec * D + cbase);
        float4 pf[8];
        #pragma unroll
        for (int i = 0; i < 8; i++) pf[i] = p4[i];
        #pragma unroll
        for (int i = 0; i < 8; i++) {
            float4 x = pf[i];
            int c = cbase + i * 4;
            char* A = smem + ((c >> 6) ? A1T : A0T);
            *(uint2*)(A + row * ROWSTRIDE + (c & 63) * 2) =
                make_uint2(pack_f16(x.x, x.y), pack_f16(x.z, x.w));
        }
    }
    CP_WAIT0();
    __syncthreads();

    float acc[2][2][4][4];
    #pragma unroll
    for (int b = 0; b < 2; b++)
        #pragma unroll
        for (int i = 0; i < 2; i++)
            #pragma unroll
            for (int j = 0; j < 4; j++)
                #pragma unroll
                for (int q = 0; q < 4; q++) acc[b][i][j][q] = 0.f;

    // layer-1 MMA: one A tile, BOTH branches (A fragments shared)
    auto mma_l1 = [&](uint32_t Aoff) {
        uint32_t A = sb + Aoff;
        #pragma unroll
        for (int kk = 0; kk < 4; kk++) {
            uint32_t ah[2][4];
            #pragma unroll
            for (int i = 0; i < 2; i++) {
                uint32_t off = (wm * 32 + i * 16 + (lane & 15)) * ROWSTRIDE
                             + (lane >> 4) * 16 + kk * 32;
                ldsm_x4(A + off, ah[i]);
            }
            #pragma unroll
            for (int br = 0; br < 2; br++) {
                uint32_t W = sb + br * 18432;
                uint32_t boffA = (wn * 32 + ((lane >> 4) * 8) + (lane & 7)) * ROWSTRIDE
                               + ((lane >> 3) & 1) * 16 + kk * 32;
                uint32_t bh[2][4];
                ldsm_x4(W + boffA, bh[0]);
                ldsm_x4(W + boffA + 16 * ROWSTRIDE, bh[1]);
                #pragma unroll
                for (int i = 0; i < 2; i++)
                    #pragma unroll
                    for (int j = 0; j < 4; j++)
                        mma_f16(acc[br][i][j], ah[i], bh[j >> 1][(j & 1) * 2], bh[j >> 1][(j & 1) * 2 + 1]);
            }
        }
    };
    // layer-2 MMA: one branch, one H tile, one W slot
    auto mma_l2 = [&](int br, uint32_t Hoff, uint32_t Woff) {
        uint32_t A = sb + Hoff;
        uint32_t W = sb + Woff;
        #pragma unroll
        for (int kk = 0; kk < 4; kk++) {
            uint32_t ah[2][4];
            #pragma unroll
            for (int i = 0; i < 2; i++) {
                uint32_t off = (wm * 32 + i * 16 + (lane & 15)) * ROWSTRIDE
                             + (lane >> 4) * 16 + kk * 32;
                ldsm_x4(A + off, ah[i]);
            }
            uint32_t boffA = (wn * 32 + ((lane >> 4) * 8) + (lane & 7)) * ROWSTRIDE
                           + ((lane >> 3) & 1) * 16 + kk * 32;
            uint32_t bh[2][4];
            ldsm_x4(W + boffA, bh[0]);
            ldsm_x4(W + boffA + 16 * ROWSTRIDE, bh[1]);
            #pragma unroll
            for (int i = 0; i < 2; i++)
                #pragma unroll
                for (int j = 0; j < 4; j++)
                    mma_f16(acc[br][i][j], ah[i], bh[j >> 1][(j & 1) * 2], bh[j >> 1][(j & 1) * 2 + 1]);
        }
    };
    auto epilogue1 = [&](int br, uint32_t ustoff) {
        const char* ust = smem + ustoff;
        const int chunk = wn >> 1;
        char* Hh = smem + (br ? (chunk ? HE1 : HE0) : (chunk ? A1T : A0T));
        const float* b0p = bias + br * 256;
        #pragma unroll
        for (int i = 0; i < 2; i++) {
            int r0 = wm * 32 + i * 16 + (lane >> 2);
            int r1 = r0 + 8;
            #pragma unroll
            for (int j = 0; j < 4; j++) {
                int c  = wn * 32 + j * 8 + (lane & 3) * 2;
                int cl = c & 63;
                float2 bb = *(const float2*)(b0p + c);
                float2 fA = __half22float2(*(const __half2*)(ust + r0 * USTRIDE + c * 2));
                float2 fB = __half22float2(*(const __half2*)(ust + r1 * USTRIDE + c * 2));
                float v0 = leaky(acc[br][i][j][0] + fA.x + bb.x);
                float v1 = leaky(acc[br][i][j][1] + fA.y + bb.y);
                float v2 = leaky(acc[br][i][j][2] + fB.x + bb.x);
                float v3 = leaky(acc[br][i][j][3] + fB.y + bb.y);
                *(uint32_t*)(Hh + r0 * ROWSTRIDE + cl * 2) = pack_f16(v0, v1);
                *(uint32_t*)(Hh + r1 * ROWSTRIDE + cl * 2) = pack_f16(v2, v3);
            }
        }
    };

    // ---- layer 1 chunk 0 (A0 x W0e-c0, both branches) ----------------------
    mma_l1(A0T);
    __syncthreads();                          // W slots free

    // ---- reload W0e chunk1; meanwhile esum (half2) + stage UST1 ------------
    #pragma unroll
    for (int u = 0; u < 8; u++) {
        int i = tid + u * 256;
        int t = i >> 10, r = i & 1023, n = r >> 3, q = r & 7;
        cp_async16(sb + t * 18432 + n * ROWSTRIDE + q * 16,
                   (const char*)g_W0T[t] + n * 768 + 640 + q * 16);
    }
    CP_COMMIT();
    {   // per-graph edge column sums, half2: thread = (col pair, 16-row group)
        int cp = tid & 63, grp = tid >> 6;     // grp 0..3, rows grp*16..+16
        const char* A = smem + ((cp >> 5) ? A1T : A0T);
        int cl2 = (cp & 31) * 2;               // col within tile
        int rbase = grp * 16;
        int gg = (e0 + rbase) / epg;
        int split = (gg + 1) * epg - (e0 + rbase);
        if (split > 16) split = 16;
        float2 s0 = make_float2(0.f, 0.f), s1 = make_float2(0.f, 0.f);
        #pragma unroll 8
        for (int r = 0; r < 16; r++) {
            int e = e0 + rbase + r;
            if (e < E) {
                float2 f = __half22float2(*(const __half2*)(A + (rbase + r) * ROWSTRIDE + cl2 * 2));
                if (r < split) { s0.x += f.x; s0.y += f.y; }
                else           { s1.x += f.x; s1.y += f.y; }
            }
        }
        int col = cp * 2;
        atomicAdd(&g_esum[gg * 128 + col], s0.x);
        atomicAdd(&g_esum[gg * 128 + col + 1], s0.y);
        if (split < 16 && (e0 + rbase + split) < E) {
            atomicAdd(&g_esum[(gg + 1) * 128 + col], s1.x);
            atomicAdd(&g_esum[(gg + 1) * 128 + col + 1], s1.y);
        }
    }
    #pragma unroll
    for (int u = 0; u < 4; u++) {
        int i = tid + u * 256;
        int row = i >> 4, q = i & 15;
        uint4 a = *(const uint4*)(g_Us + (size_t)sidx[row] * 256 + 128 + q * 8);
        uint4 b = *(const uint4*)(g_Ur + (size_t)ridx[row] * 256 + 128 + q * 8);
        uint4 o;
        o.x = h22u(__hadd2(u2h2(a.x), u2h2(b.x)));
        o.y = h22u(__hadd2(u2h2(a.y), u2h2(b.y)));
        o.z = h22u(__hadd2(u2h2(a.z), u2h2(b.z)));
        o.w = h22u(__hadd2(u2h2(a.w), u2h2(b.w)));
        *(uint4*)(smem + US1 + row * USTRIDE + q * 16) = o;
    }
    CP_WAIT0();
    __syncthreads();

    // ---- layer 1 chunk 1 (A1 x W0e-c1) -------------------------------------
    mma_l1(A1T);
    __syncthreads();

    // ---- reload W1n (c0 -> WS0, c1 -> WS1); epilogues write H --------------
    #pragma unroll
    for (int u = 0; u < 8; u++) {
        int i = tid + u * 256;
        int t = i >> 10, r = i & 1023, n = r >> 3, q = r & 7;
        cp_async16(sb + t * 18432 + n * ROWSTRIDE + q * 16,
                   (const char*)g_W1T[0] + n * 256 + t * 128 + q * 16);
    }
    CP_COMMIT();
    epilogue1(0, US0);    // H-node -> A0/A1 (A consumed)
    epilogue1(1, US1);    // H-edge -> HE0/HE1
    CP_WAIT0();
    __syncthreads();

    // ---- layer 2 branch 0 (node messages) ----------------------------------
    #pragma unroll
    for (int i = 0; i < 2; i++)
        #pragma unroll
        for (int j = 0; j < 4; j++)
            #pragma unroll
            for (int q = 0; q < 4; q++) acc[0][i][j][q] = 0.f;
    mma_l2(0, A0T, WS0);
    mma_l2(0, A1T, WS1);
    __syncthreads();

    // ---- reload W1e; stage node-out into STG; scatter ----------------------
    #pragma unroll
    for (int u = 0; u < 8; u++) {
        int i = tid + u * 256;
        int t = i >> 10, r = i & 1023, n = r >> 3, q = r & 7;
        cp_async16(sb + t * 18432 + n * ROWSTRIDE + q * 16,
                   (const char*)g_W1T[1] + n * 256 + t * 128 + q * 16);
    }
    CP_COMMIT();
    {
        char* stag = smem + STG;
        const float* b1p = bias + 128;
        #pragma unroll
        for (int i = 0; i < 2; i++) {
            int r0 = wm * 32 + i * 16 + (lane >> 2);
            #pragma unroll
            for (int j = 0; j < 4; j++) {
                int c = wn * 32 + j * 8 + (lane & 3) * 2;
                float2 bb = *(const float2*)(b1p + c);
                *(float2*)(stag + r0 * STAG_STRIDE + c * 4) =
                    make_float2(leaky(acc[0][i][j][0] + bb.x), leaky(acc[0][i][j][1] + bb.y));
                *(float2*)(stag + (r0 + 8) * STAG_STRIDE + c * 4) =
                    make_float2(leaky(acc[0][i][j][2] + bb.x), leaky(acc[0][i][j][3] + bb.y));
            }
        }
    }
    CP_WAIT0();
    __syncthreads();
    FENCE_PROXY_ASYNC();
    if (tid < 64 && (e0 + tid) < E) {
        const float* dst = new_nodes + (size_t)ridx[tid] * D;
        asm volatile("cp.reduce.async.bulk.global.shared::cta.bulk_group.add.f32 [%0], [%1], %2;"
                     :: "l"(dst), "r"(sb + STG + tid * STAG_STRIDE), "r"(512) : "memory");
    }
    asm volatile("cp.async.bulk.commit_group;" ::: "memory");

    // ---- layer 2 branch 1 (edge update) ------------------------------------
    #pragma unroll
    for (int i = 0; i < 2; i++)
        #pragma unroll
        for (int j = 0; j < 4; j++)
            #pragma unroll
            for (int q = 0; q < 4; q++) acc[1][i][j][q] = 0.f;
    mma_l2(1, HE0, WS0);
    mma_l2(1, HE1, WS1);

    {
        const float* b1p = bias + 384;
        #pragma unroll
        for (int i = 0; i < 2; i++) {
            int r0 = wm * 32 + i * 16 + (lane >> 2);
            #pragma unroll
            for (int j = 0; j < 4; j++) {
                int c = wn * 32 + j * 8 + (lane & 3) * 2;
                float2 bb = *(const float2*)(b1p + c);
                int eA = e0 + r0, eB = eA + 8;
                if (eA < E)
                    *(float2*)(new_edges + (size_t)eA * D + c) =
                        make_float2(leaky(acc[1][i][j][0] + bb.x), leaky(acc[1][i][j][1] + bb.y));
                if (eB < E)
                    *(float2*)(new_edges + (size_t)eB * D + c) =
                        make_float2(leaky(acc[1][i][j][2] + bb.x), leaky(acc[1][i][j][3] + bb.y));
            }
        }
    }
    asm volatile("cp.async.bulk.wait_group.read 0;" ::: "memory");
}

// ============================================================================
extern "C" void kernel_launch(void* const* d_in, const int* in_sizes, int n_in,
                              void* d_out, int out_size)
{
    const float* nodes     = (const float*)d_in[0];
    const float* edges     = (const float*)d_in[1];
    const float* globals_  = (const float*)d_in[2];
    const int*   senders   = (const int*)d_in[3];
    const int*   receivers = (const int*)d_in[4];

    const float* node_W0 = (const float*)d_in[7];
    const float* node_b0 = (const float*)d_in[8];
    const float* node_W1 = (const float*)d_in[9];
    const float* node_b1 = (const float*)d_in[10];
    const float* edge_W0 = (const float*)d_in[11];
    const float* edge_b0 = (const float*)d_in[12];
    const float* edge_W1 = (const float*)d_in[13];
    const float* edge_b1 = (const float*)d_in[14];
    const float* glob_W0 = (const float*)d_in[15];
    const float* glob_b0 = (const float*)d_in[16];
    const float* glob_W1 = (const float*)d_in[17];
    const float* glob_b1 = (const float*)d_in[18];
    const float* gnode_W0 = (const float*)d_in[19];
    const float* gnode_b0 = (const float*)d_in[20];
    const float* gnode_W1 = (const float*)d_in[21];
    const float* gnode_b1 = (const float*)d_in[22];
    const float* gedge_W0 = (const float*)d_in[23];
    const float* gedge_b0 = (const float*)d_in[24];
    const float* gedge_W1 = (const float*)d_in[25];
    const float* gedge_b1 = (const float*)d_in[26];
    const float* fin_W0 = (const float*)d_in[27];
    const float* fin_b0 = (const float*)d_in[28];
    const float* fin_W1 = (const float*)d_in[29];
    const float* fin_b1 = (const float*)d_in[30];

    const int N = in_sizes[0] / D;
    const int E = in_sizes[3];
    const int G = in_sizes[5];
    const int epg = E / G;
    const int npg = N / G;

    float* new_nodes  = (float*)d_out;
    float* new_edges  = new_nodes + (size_t)N * D;
    float* new_global = new_edges + (size_t)E * D;

    // [0] zero segment-sum targets
    int n4 = N * D / 4;
    zero_nodes_kernel<<<(n4 + 255) / 256, 256>>>((float4*)new_nodes, n4);
    void* p;
    cudaGetSymbolAddress(&p, g_esum);
    cudaMemsetAsync(p, 0, 256 * 128 * sizeof(float), 0);
    cudaGetSymbolAddress(&p, g_nsum);
    cudaMemsetAsync(p, 0, 256 * 128 * sizeof(float), 0);

    // [1] weight prep
    prep_weights<<<512, 256>>>(node_W0, node_W1, edge_W0, edge_W1);

    // [2] precompute per-node layer-1 partials + per-graph node sums
    cudaFuncSetAttribute(precompute_u_kernel,
                         cudaFuncAttributeMaxDynamicSharedMemorySize, P_SMEM);
    precompute_u_kernel<<<(N + 127) / 128, 512, P_SMEM>>>(nodes, N, npg);

    // [3] main edge kernel (also accumulates g_esum)
    cudaFuncSetAttribute(edge_mma_kernel,
                         cudaFuncAttributeMaxDynamicSharedMemorySize, E_SMEM);
    int grid = (E + 63) / 64;
    edge_mma_kernel<<<grid, 256, E_SMEM>>>(
        edges, senders, receivers,
        node_b0, node_b1, edge_b0, edge_b1,
        new_nodes, new_edges, E, epg);

    // [4] global branch MLPs (needs g_esum/g_nsum)
    dim3 gb(G, 3);
    global_branch_kernel<<<gb, 256>>>(globals_,
        glob_W0, glob_b0, glob_W1, glob_b1,
        gnode_W0, gnode_b0, gnode_W1, gnode_b1,
        gedge_W0, gedge_b0, gedge_W1, gedge_b1);

    // [5] final global MLP
    global_final_kernel<<<G, 256>>>(fin_W0, fin_b0, fin_W1, fin_b1, new_global);
}

// round 14
// speedup vs baseline: 1.0177x; 1.0177x over previous
#include <cuda_runtime.h>
#include <cuda_fp16.h>
#include <cstdint>

#define D 128
#define ROWSTRIDE 144
#define NMAX 51200

// ---- precompute kernel smem layout (2 A tiles + 2 W slots) ----
#define P_A0   0
#define P_A1   18432
#define P_W0   36864
#define P_SMEM 73728

// ---- edge kernel smem layout (2 CTAs/SM) ----
#define WS0   0                            // W slot 0 (128n x 64k, 18432B)
#define WS1   18432                        // W slot 1
#define A0T   36864                        // A/H tile c0 (64 x 144 = 9216)
#define A1T   46080                        // A/H tile c1
#define HE0   55296                        // H-edge c0
#define HE1   64512                        // H-edge c1
#define US0   73728                        // U staging br0 (64 x 272 = 17408)
#define US1   91136                        // U staging br1
#define STG   73728                        // node-out staging (64 x 528) reuses US
#define IDXO  108544                       // sidx[64], ridx[64]
#define BIASO 109056                       // 512 floats
#define E_SMEM 111104
#define USTRIDE 272
#define STAG_STRIDE 528

__device__ __forceinline__ uint32_t smem_u32(const void* p) {
    uint32_t a;
    asm("{ .reg .u64 t; cvta.to.shared.u64 t, %1; cvt.u32.u64 %0, t; }" : "=r"(a) : "l"(p));
    return a;
}
__device__ __forceinline__ float leaky(float x) { return x > 0.0f ? x : 0.01f * x; }
__device__ __forceinline__ uint32_t pack_f16(float a, float b) {
    __half2 t = __floats2half2_rn(a, b);
    return reinterpret_cast<uint32_t&>(t);
}
__device__ __forceinline__ __half2 u2h2(uint32_t u) { return reinterpret_cast<__half2&>(u); }
__device__ __forceinline__ uint32_t h22u(__half2 h) { return reinterpret_cast<uint32_t&>(h); }
__device__ __forceinline__ void ldsm_x4(uint32_t addr, uint32_t r[4]) {
    asm volatile("ldmatrix.sync.aligned.m8n8.x4.shared.b16 {%0,%1,%2,%3}, [%4];"
                 : "=r"(r[0]), "=r"(r[1]), "=r"(r[2]), "=r"(r[3]) : "r"(addr));
}
__device__ __forceinline__ void mma_f16(float* c, const uint32_t* a, uint32_t b0, uint32_t b1) {
    asm volatile("mma.sync.aligned.m16n8k16.row.col.f32.f16.f16.f32 "
                 "{%0,%1,%2,%3}, {%4,%5,%6,%7}, {%8,%9}, {%0,%1,%2,%3};"
                 : "+f"(c[0]), "+f"(c[1]), "+f"(c[2]), "+f"(c[3])
                 : "r"(a[0]), "r"(a[1]), "r"(a[2]), "r"(a[3]), "r"(b0), "r"(b1));
}
__device__ __forceinline__ void cp_async16(uint32_t saddr, const void* gaddr) {
    asm volatile("cp.async.cg.shared.global [%0], [%1], 16;" :: "r"(saddr), "l"(gaddr));
}
#define CP_COMMIT()  asm volatile("cp.async.commit_group;" ::: "memory")
#define CP_WAIT0()   asm volatile("cp.async.wait_group 0;" ::: "memory")
#define FENCE_PROXY_ASYNC() asm volatile("fence.proxy.async.shared::cta;" ::: "memory")

// ============================================================================
// Device scratch
// ============================================================================
__device__ __half g_W0T[2][128 * 384];   // [branch][n(out)][k] transposed fp16
__device__ __half g_W1T[2][128 * 128];
__device__ __half g_Us[NMAX * 256];      // per-node sender partials [n][br*128+c]
__device__ __half g_Ur[NMAX * 256];      // per-node receiver partials
__device__ float g_nsum[256 * 128];      // per-graph node sums
__device__ float g_esum[256 * 128];      // per-graph edge sums
__device__ float g_cat[256][384];        // concat of 3 global-branch MLPs

// ============================================================================
// [0] fused init: zero new_nodes + zero nsum/esum + weight prep
// ============================================================================
__global__ void init_kernel(const float* __restrict__ nW0, const float* __restrict__ nW1,
                            const float* __restrict__ eW0, const float* __restrict__ eW1,
                            float4* __restrict__ zp, int n4)
{
    int i = blockIdx.x * 256 + threadIdx.x;
    float4 z = make_float4(0.f, 0.f, 0.f, 0.f);
    if (i < n4) zp[i] = z;
    if (i < 8192) {
        ((float4*)g_esum)[i] = z;
        ((float4*)g_nsum)[i] = z;
    }
    if (i < 98304) {                      // W0T: 2 * 128*384
        int b = i / 49152, r = i % 49152;
        int n = r / 384, k = r % 384;
        g_W0T[b][n * 384 + k] = __float2half_rn((b ? eW0 : nW0)[k * 128 + n]);
    } else if (i < 131072) {              // W1T: 2 * 128*128
        int j = i - 98304;
        int b = j / 16384, r = j % 16384;
        int n = r / 128, k = r % 128;
        g_W1T[b][n * 128 + k] = __float2half_rn((b ? eW1 : nW1)[k * 128 + n]);
    }
}

// ============================================================================
// [1] precompute U_s / U_r + per-graph node sums: grid N/128, 512 thr, 2 CTAs/SM
// ============================================================================
__global__ __launch_bounds__(512, 2)
void precompute_u_kernel(const float* __restrict__ nodes, int N, int npg)
{
    extern __shared__ char smem[];
    const uint32_t sb = smem_u32(smem);
    const int tid = threadIdx.x;
    const int wid = tid >> 5;
    const int lane = tid & 31;
    const int wm = wid >> 2, wn = wid & 3;
    const int n0 = blockIdx.x * 128;

    // A: nodes rows -> fp16 tiles P_A0/P_A1
    {
        int row = tid >> 2;
        int nn = n0 + row; if (nn >= N) nn = N - 1;
        int cbase = (tid & 3) * 32;
        const float4* p4 = (const float4*)(nodes + (size_t)nn * D + cbase);
        float4 pf[8];
        #pragma unroll
        for (int i = 0; i < 8; i++) pf[i] = p4[i];
        #pragma unroll
        for (int i = 0; i < 8; i++) {
            float4 x = pf[i];
            int c = cbase + i * 4;
            char* A = smem + ((c >> 6) ? P_A1 : P_A0);
            *(uint2*)(A + row * ROWSTRIDE + (c & 63) * 2) =
                make_uint2(pack_f16(x.x, x.y), pack_f16(x.z, x.w));
        }
    }
    __syncthreads();

    // per-graph node column sums (from fp16 A tiles)
    {
        int col = tid & 127, grp = tid >> 7;
        const char* A = smem + ((col >> 6) ? P_A1 : P_A0);
        int cl = col & 63;
        int rbase = grp * 32;
        int gg = (n0 + rbase) / npg;
        int split = (gg + 1) * npg - (n0 + rbase);
        if (split > 32) split = 32;
        float s0 = 0.f, s1 = 0.f;
        #pragma unroll 8
        for (int r = 0; r < 32; r++) {
            int n = n0 + rbase + r;
            if (n < N) {
                float v = __half2float(*(const __half*)(A + (rbase + r) * ROWSTRIDE + cl * 2));
                if (r < split) s0 += v; else s1 += v;
            }
        }
        atomicAdd(&g_nsum[gg * 128 + col], s0);
        if (split < 32 && (n0 + rbase + split) < N)
            atomicAdd(&g_nsum[(gg + 1) * 128 + col], s1);
    }

    #pragma unroll 1
    for (int g = 0; g < 4; g++) {
        int tab = g >> 1, br = g & 1;

        #pragma unroll
        for (int u = 0; u < 4; u++) {
            int i = tid + u * 512;
            int t = i >> 10, r = i & 1023, n = r >> 3, q = r & 7;
            cp_async16(sb + P_W0 + t * 18432 + n * ROWSTRIDE + q * 16,
                       (const char*)g_W0T[br] + n * 768 + tab * 256 + t * 128 + q * 16);
        }
        CP_COMMIT();
        CP_WAIT0();
        __syncthreads();

        float acc[2][4][4];
        #pragma unroll
        for (int i = 0; i < 2; i++)
            #pragma unroll
            for (int j = 0; j < 4; j++)
                #pragma unroll
                for (int q = 0; q < 4; q++) acc[i][j][q] = 0.f;

        #pragma unroll
        for (int kc = 0; kc < 2; kc++) {
            uint32_t A = sb + (kc ? P_A1 : P_A0);
            uint32_t W = sb + P_W0 + kc * 18432;
            #pragma unroll
            for (int kk = 0; kk < 4; kk++) {
                uint32_t ah[2][4];
                #pragma unroll
                for (int i = 0; i < 2; i++) {
                    uint32_t off = (wm * 32 + i * 16 + (lane & 15)) * ROWSTRIDE
                                 + (lane >> 4) * 16 + kk * 32;
                    ldsm_x4(A + off, ah[i]);
                }
                uint32_t boffA = (wn * 32 + ((lane >> 4) * 8) + (lane & 7)) * ROWSTRIDE
                               + ((lane >> 3) & 1) * 16 + kk * 32;
                uint32_t bh[2][4];
                ldsm_x4(W + boffA, bh[0]);
                ldsm_x4(W + boffA + 16 * ROWSTRIDE, bh[1]);
                #pragma unroll
                for (int i = 0; i < 2; i++)
                    #pragma unroll
                    for (int j = 0; j < 4; j++)
                        mma_f16(acc[i][j], ah[i], bh[j >> 1][(j & 1) * 2], bh[j >> 1][(j & 1) * 2 + 1]);
            }
        }

        __half* U = tab ? g_Ur : g_Us;
        #pragma unroll
        for (int i = 0; i < 2; i++) {
            int r0 = wm * 32 + i * 16 + (lane >> 2);
            int nA = n0 + r0, nB = nA + 8;
            #pragma unroll
            for (int j = 0; j < 4; j++) {
                int c = wn * 32 + j * 8 + (lane & 3) * 2;
                if (nA < N)
                    *(uint32_t*)(U + (size_t)nA * 256 + br * 128 + c) =
                        pack_f16(acc[i][j][0], acc[i][j][1]);
                if (nB < N)
                    *(uint32_t*)(U + (size_t)nB * 256 + br * 128 + c) =
                        pack_f16(acc[i][j][2], acc[i][j][3]);
            }
        }
        __syncthreads();
    }
}

// ============================================================================
// [3] global branch MLPs: grid (G, 3), block 256 (k-split halves) -> g_cat
// ============================================================================
__global__ void global_branch_kernel(const float* __restrict__ globals_,
                                     const float* gW0, const float* gb0, const float* gW1, const float* gb1,
                                     const float* nW0, const float* nb0, const float* nW1, const float* nb1,
                                     const float* eW0, const float* eb0, const float* eW1, const float* eb1)
{
    __shared__ float in[D];
    __shared__ float h[D];
    __shared__ float part[2][D];
    int g = blockIdx.x, b = blockIdx.y;
    int d = threadIdx.x & 127, half = threadIdx.x >> 7;
    int k0 = half * 64;

    const float *W0, *b0, *W1, *b1;
    if (b == 0)      { W0 = gW0; b0 = gb0; W1 = gW1; b1 = gb1;
                       if (!half) in[d] = globals_[(size_t)g * D + d]; }
    else if (b == 1) { W0 = nW0; b0 = nb0; W1 = nW1; b1 = nb1;
                       if (!half) in[d] = g_nsum[g * D + d]; }
    else             { W0 = eW0; b0 = eb0; W1 = eW1; b1 = eb1;
                       if (!half) in[d] = g_esum[g * D + d]; }
    __syncthreads();

    float a0 = 0.f, a1 = 0.f, a2 = 0.f, a3 = 0.f;
    #pragma unroll 4
    for (int k = k0; k < k0 + 64; k += 4) {
        a0 = fmaf(in[k],     __ldg(W0 + k * D + d),       a0);
        a1 = fmaf(in[k + 1], __ldg(W0 + (k + 1) * D + d), a1);
        a2 = fmaf(in[k + 2], __ldg(W0 + (k + 2) * D + d), a2);
        a3 = fmaf(in[k + 3], __ldg(W0 + (k + 3) * D + d), a3);
    }
    part[half][d] = (a0 + a1) + (a2 + a3);
    __syncthreads();
    if (!half) h[d] = leaky(part[0][d] + part[1][d] + __ldg(b0 + d));
    __syncthreads();

    a0 = a1 = a2 = a3 = 0.f;
    #pragma unroll 4
    for (int k = k0; k < k0 + 64; k += 4) {
        a0 = fmaf(h[k],     __ldg(W1 + k * D + d),       a0);
        a1 = fmaf(h[k + 1], __ldg(W1 + (k + 1) * D + d), a1);
        a2 = fmaf(h[k + 2], __ldg(W1 + (k + 2) * D + d), a2);
        a3 = fmaf(h[k + 3], __ldg(W1 + (k + 3) * D + d), a3);
    }
    part[half][d] = (a0 + a1) + (a2 + a3);
    __syncthreads();
    if (!half)
        g_cat[g][b * D + d] = leaky(part[0][d] + part[1][d] + __ldg(b1 + d));
}

// ============================================================================
// [4] final global MLP: grid G, block 256 (k-split halves)
// ============================================================================
__global__ void global_final_kernel(const float* fW0, const float* fb0,
                                    const float* fW1, const float* fb1,
                                    float* __restrict__ out_global)
{
    __shared__ float cat[3 * D];
    __shared__ float h[D];
    __shared__ float part[2][D];
    int g = blockIdx.x;
    int d = threadIdx.x & 127, half = threadIdx.x >> 7;

    if (!half) {
        cat[d]         = g_cat[g][d];
        cat[D + d]     = g_cat[g][D + d];
        cat[2 * D + d] = g_cat[g][2 * D + d];
    }
    __syncthreads();

    float a0 = 0.f, a1 = 0.f, a2 = 0.f, a3 = 0.f;
    int k0 = half * 192;
    #pragma unroll 4
    for (int k = k0; k < k0 + 192; k += 4) {
        a0 = fmaf(cat[k],     __ldg(fW0 + k * D + d),       a0);
        a1 = fmaf(cat[k + 1], __ldg(fW0 + (k + 1) * D + d), a1);
        a2 = fmaf(cat[k + 2], __ldg(fW0 + (k + 2) * D + d), a2);
        a3 = fmaf(cat[k + 3], __ldg(fW0 + (k + 3) * D + d), a3);
    }
    part[half][d] = (a0 + a1) + (a2 + a3);
    __syncthreads();
    if (!half) h[d] = leaky(part[0][d] + part[1][d] + __ldg(fb0 + d));
    __syncthreads();

    a0 = a1 = a2 = a3 = 0.f;
    int k1 = half * 64;
    #pragma unroll 4
    for (int k = k1; k < k1 + 64; k += 4) {
        a0 = fmaf(h[k],     __ldg(fW1 + k * D + d),       a0);
        a1 = fmaf(h[k + 1], __ldg(fW1 + (k + 1) * D + d), a1);
        a2 = fmaf(h[k + 2], __ldg(fW1 + (k + 2) * D + d), a2);
        a3 = fmaf(h[k + 3], __ldg(fW1 + (k + 3) * D + d), a3);
    }
    part[half][d] = (a0 + a1) + (a2 + a3);
    __syncthreads();
    if (!half)
        out_global[(size_t)g * D + d] = leaky(part[0][d] + part[1][d] + __ldg(fb1 + d));
}

// ============================================================================
// [2] main fused edge kernel: M=64 edges/CTA, 256 threads, 2 CTAs/SM. (R12)
// ============================================================================
__global__ __launch_bounds__(256, 2)
void edge_mma_kernel(const float* __restrict__ edges,
                     const int*   __restrict__ senders,
                     const int*   __restrict__ receivers,
                     const float* __restrict__ nb0f, const float* __restrict__ nb1f,
                     const float* __restrict__ eb0f, const float* __restrict__ eb1f,
                     float* __restrict__ new_nodes,
                     float* __restrict__ new_edges,
                     int E, int epg)
{
    extern __shared__ char smem[];
    const uint32_t sb = smem_u32(smem);
    const int tid  = threadIdx.x;
    const int wid  = tid >> 5;
    const int lane = tid & 31;
    const int wm   = wid >> 2;   // 0..1 (M offset wm*32)
    const int wn   = wid & 3;    // 0..3 (N offset wn*32)
    const int e0   = blockIdx.x * 64;

    int*   sidx = (int*)(smem + IDXO);
    int*   ridx = (int*)(smem + IDXO + 256);
    float* bias = (float*)(smem + BIASO);

    // cp.async W0e chunk0 -> slots (br0 -> WS0, br1 -> WS1)
    #pragma unroll
    for (int u = 0; u < 8; u++) {
        int i = tid + u * 256;
        int t = i >> 10, r = i & 1023, n = r >> 3, q = r & 7;
        cp_async16(sb + t * 18432 + n * ROWSTRIDE + q * 16,
                   (const char*)g_W0T[t] + n * 768 + 512 + q * 16);
    }
    CP_COMMIT();

    if (tid < 64) {
        int ec = (e0 + tid < E) ? e0 + tid : E - 1;
        sidx[tid] = senders[ec];
        ridx[tid] = receivers[ec];
    }
    if (tid < 128) { bias[tid] = nb0f[tid]; bias[256 + tid] = eb0f[tid]; }
    else { int t = tid - 128; bias[128 + t] = nb1f[t]; bias[384 + t] = eb1f[t]; }

    // stage U branch-0 (indices straight from global; hides behind loads+L1 MMA)
    #pragma unroll
    for (int u = 0; u < 4; u++) {
        int i = tid + u * 256;
        int row = i >> 4, q = i & 15;
        int ec = (e0 + row < E) ? e0 + row : E - 1;
        int s = __ldg(senders + ec);
        int r = __ldg(receivers + ec);
        uint4 a = *(const uint4*)(g_Us + (size_t)s * 256 + q * 8);
        uint4 b = *(const uint4*)(g_Ur + (size_t)r * 256 + q * 8);
        uint4 o;
        o.x = h22u(__hadd2(u2h2(a.x), u2h2(b.x)));
        o.y = h22u(__hadd2(u2h2(a.y), u2h2(b.y)));
        o.z = h22u(__hadd2(u2h2(a.z), u2h2(b.z)));
        o.w = h22u(__hadd2(u2h2(a.w), u2h2(b.w)));
        *(uint4*)(smem + US0 + row * USTRIDE + q * 16) = o;
    }

    // A: edge rows (contiguous) -> fp16 tiles A0/A1
    {
        int row = tid >> 2;
        int ec = (e0 + row < E) ? e0 + row : E - 1;
        int cbase = (tid & 3) * 32;
        const float4* p4 = (const float4*)(edges + (size_t)ec * D + cbase);
        float4 pf[8];
        #pragma unroll
        for (int i = 0; i < 8; i++) pf[i] = p4[i];
        #pragma unroll
        for (int i = 0; i < 8; i++) {
            float4 x = pf[i];
            int c = cbase + i * 4;
            char* A = smem + ((c >> 6) ? A1T : A0T);
            *(uint2*)(A + row * ROWSTRIDE + (c & 63) * 2) =
                make_uint2(pack_f16(x.x, x.y), pack_f16(x.z, x.w));
        }
    }
    CP_WAIT0();
    __syncthreads();

    float acc[2][2][4][4];
    #pragma unroll
    for (int b = 0; b < 2; b++)
        #pragma unroll
        for (int i = 0; i < 2; i++)
            #pragma unroll
            for (int j = 0; j < 4; j++)
                #pragma unroll
                for (int q = 0; q < 4; q++) acc[b][i][j][q] = 0.f;

    // layer-1 MMA: one A tile, BOTH branches (A fragments shared)
    auto mma_l1 = [&](uint32_t Aoff) {
        uint32_t A = sb + Aoff;
        #pragma unroll
        for (int kk = 0; kk < 4; kk++) {
            uint32_t ah[2][4];
            #pragma unroll
            for (int i = 0; i < 2; i++) {
                uint32_t off = (wm * 32 + i * 16 + (lane & 15)) * ROWSTRIDE
                             + (lane >> 4) * 16 + kk * 32;
                ldsm_x4(A + off, ah[i]);
            }
            #pragma unroll
            for (int br = 0; br < 2; br++) {
                uint32_t W = sb + br * 18432;
                uint32_t boffA = (wn * 32 + ((lane >> 4) * 8) + (lane & 7)) * ROWSTRIDE
                               + ((lane >> 3) & 1) * 16 + kk * 32;
                uint32_t bh[2][4];
                ldsm_x4(W + boffA, bh[0]);
                ldsm_x4(W + boffA + 16 * ROWSTRIDE, bh[1]);
                #pragma unroll
                for (int i = 0; i < 2; i++)
                    #pragma unroll
                    for (int j = 0; j < 4; j++)
                        mma_f16(acc[br][i][j], ah[i], bh[j >> 1][(j & 1) * 2], bh[j >> 1][(j & 1) * 2 + 1]);
            }
        }
    };
    // layer-2 MMA: one branch, one H tile, one W slot
    auto mma_l2 = [&](int br, uint32_t Hoff, uint32_t Woff) {
        uint32_t A = sb + Hoff;
        uint32_t W = sb + Woff;
        #pragma unroll
        for (int kk = 0; kk < 4; kk++) {
            uint32_t ah[2][4];
            #pragma unroll
            for (int i = 0; i < 2; i++) {
                uint32_t off = (wm * 32 + i * 16 + (lane & 15)) * ROWSTRIDE
                             + (lane >> 4) * 16 + kk * 32;
                ldsm_x4(A + off, ah[i]);
            }
            uint32_t boffA = (wn * 32 + ((lane >> 4) * 8) + (lane & 7)) * ROWSTRIDE
                           + ((lane >> 3) & 1) * 16 + kk * 32;
            uint32_t bh[2][4];
            ldsm_x4(W + boffA, bh[0]);
            ldsm_x4(W + boffA + 16 * ROWSTRIDE, bh[1]);
            #pragma unroll
            for (int i = 0; i < 2; i++)
                #pragma unroll
                for (int j = 0; j < 4; j++)
                    mma_f16(acc[br][i][j], ah[i], bh[j >> 1][(j & 1) * 2], bh[j >> 1][(j & 1) * 2 + 1]);
        }
    };
    auto epilogue1 = [&](int br, uint32_t ustoff) {
        const char* ust = smem + ustoff;
        const int chunk = wn >> 1;
        char* Hh = smem + (br ? (chunk ? HE1 : HE0) : (chunk ? A1T : A0T));
        const float* b0p = bias + br * 256;
        #pragma unroll
        for (int i = 0; i < 2; i++) {
            int r0 = wm * 32 + i * 16 + (lane >> 2);
            int r1 = r0 + 8;
            #pragma unroll
            for (int j = 0; j < 4; j++) {
                int c  = wn * 32 + j * 8 + (lane & 3) * 2;
                int cl = c & 63;
                float2 bb = *(const float2*)(b0p + c);
                float2 fA = __half22float2(*(const __half2*)(ust + r0 * USTRIDE + c * 2));
                float2 fB = __half22float2(*(const __half2*)(ust + r1 * USTRIDE + c * 2));
                float v0 = leaky(acc[br][i][j][0] + fA.x + bb.x);
                float v1 = leaky(acc[br][i][j][1] + fA.y + bb.y);
                float v2 = leaky(acc[br][i][j][2] + fB.x + bb.x);
                float v3 = leaky(acc[br][i][j][3] + fB.y + bb.y);
                *(uint32_t*)(Hh + r0 * ROWSTRIDE + cl * 2) = pack_f16(v0, v1);
                *(uint32_t*)(Hh + r1 * ROWSTRIDE + cl * 2) = pack_f16(v2, v3);
            }
        }
    };

    // ---- layer 1 chunk 0 (A0 x W0e-c0, both branches) ----------------------
    mma_l1(A0T);
    __syncthreads();                          // W slots free

    // ---- reload W0e chunk1; meanwhile esum (scalar) + stage UST1 -----------
    #pragma unroll
    for (int u = 0; u < 8; u++) {
        int i = tid + u * 256;
        int t = i >> 10, r = i & 1023, n = r >> 3, q = r & 7;
        cp_async16(sb + t * 18432 + n * ROWSTRIDE + q * 16,
                   (const char*)g_W0T[t] + n * 768 + 640 + q * 16);
    }
    CP_COMMIT();
    {   // per-graph edge column sums (reads A0/A1)
        int col = tid & 127, grp = tid >> 7;   // grp 0..1, rows grp*32..+31
        const char* A = smem + ((col >> 6) ? A1T : A0T);
        int cl = col & 63;
        int rbase = grp * 32;
        int gg = (e0 + rbase) / epg;
        int split = (gg + 1) * epg - (e0 + rbase);
        if (split > 32) split = 32;
        float s0 = 0.f, s1 = 0.f;
        #pragma unroll 8
        for (int r = 0; r < 32; r++) {
            int e = e0 + rbase + r;
            if (e < E) {
                float v = __half2float(*(const __half*)(A + (rbase + r) * ROWSTRIDE + cl * 2));
                if (r < split) s0 += v; else s1 += v;
            }
        }
        atomicAdd(&g_esum[gg * 128 + col], s0);
        if (split < 32 && (e0 + rbase + split) < E)
            atomicAdd(&g_esum[(gg + 1) * 128 + col], s1);
    }
    #pragma unroll
    for (int u = 0; u < 4; u++) {
        int i = tid + u * 256;
        int row = i >> 4, q = i & 15;
        uint4 a = *(const uint4*)(g_Us + (size_t)sidx[row] * 256 + 128 + q * 8);
        uint4 b = *(const uint4*)(g_Ur + (size_t)ridx[row] * 256 + 128 + q * 8);
        uint4 o;
        o.x = h22u(__hadd2(u2h2(a.x), u2h2(b.x)));
        o.y = h22u(__hadd2(u2h2(a.y), u2h2(b.y)));
        o.z = h22u(__hadd2(u2h2(a.z), u2h2(b.z)));
        o.w = h22u(__hadd2(u2h2(a.w), u2h2(b.w)));
        *(uint4*)(smem + US1 + row * USTRIDE + q * 16) = o;
    }
    CP_WAIT0();
    __syncthreads();

    // ---- layer 1 chunk 1 (A1 x W0e-c1) -------------------------------------
    mma_l1(A1T);
    __syncthreads();

    // ---- reload W1n (c0 -> WS0, c1 -> WS1); epilogues write H --------------
    #pragma unroll
    for (int u = 0; u < 8; u++) {
        int i = tid + u * 256;
        int t = i >> 10, r = i & 1023, n = r >> 3, q = r & 7;
        cp_async16(sb + t * 18432 + n * ROWSTRIDE + q * 16,
                   (const char*)g_W1T[0] + n * 256 + t * 128 + q * 16);
    }
    CP_COMMIT();
    epilogue1(0, US0);    // H-node -> A0/A1 (A consumed)
    epilogue1(1, US1);    // H-edge -> HE0/HE1
    CP_WAIT0();
    __syncthreads();

    // ---- layer 2 branch 0 (node messages) ----------------------------------
    #pragma unroll
    for (int i = 0; i < 2; i++)
        #pragma unroll
        for (int j = 0; j < 4; j++)
            #pragma unroll
            for (int q = 0; q < 4; q++) acc[0][i][j][q] = 0.f;
    mma_l2(0, A0T, WS0);
    mma_l2(0, A1T, WS1);
    __syncthreads();

    // ---- reload W1e; stage node-out into STG; scatter ----------------------
    #pragma unroll
    for (int u = 0; u < 8; u++) {
        int i = tid + u * 256;
        int t = i >> 10, r = i & 1023, n = r >> 3, q = r & 7;
        cp_async16(sb + t * 18432 + n * ROWSTRIDE + q * 16,
                   (const char*)g_W1T[1] + n * 256 + t * 128 + q * 16);
    }
    CP_COMMIT();
    {
        char* stag = smem + STG;
        const float* b1p = bias + 128;
        #pragma unroll
        for (int i = 0; i < 2; i++) {
            int r0 = wm * 32 + i * 16 + (lane >> 2);
            #pragma unroll
            for (int j = 0; j < 4; j++) {
                int c = wn * 32 + j * 8 + (lane & 3) * 2;
                float2 bb = *(const float2*)(b1p + c);
                *(float2*)(stag + r0 * STAG_STRIDE + c * 4) =
                    make_float2(leaky(acc[0][i][j][0] + bb.x), leaky(acc[0][i][j][1] + bb.y));
                *(float2*)(stag + (r0 + 8) * STAG_STRIDE + c * 4) =
                    make_float2(leaky(acc[0][i][j][2] + bb.x), leaky(acc[0][i][j][3] + bb.y));
            }
        }
    }
    CP_WAIT0();
    __syncthreads();
    FENCE_PROXY_ASYNC();
    if (tid < 64 && (e0 + tid) < E) {
        const float* dst = new_nodes + (size_t)ridx[tid] * D;
        asm volatile("cp.reduce.async.bulk.global.shared::cta.bulk_group.add.f32 [%0], [%1], %2;"
                     :: "l"(dst), "r"(sb + STG + tid * STAG_STRIDE), "r"(512) : "memory");
    }
    asm volatile("cp.async.bulk.commit_group;" ::: "memory");

    // ---- layer 2 branch 1 (edge update) ------------------------------------
    #pragma unroll
    for (int i = 0; i < 2; i++)
        #pragma unroll
        for (int j = 0; j < 4; j++)
            #pragma unroll
            for (int q = 0; q < 4; q++) acc[1][i][j][q] = 0.f;
    mma_l2(1, HE0, WS0);
    mma_l2(1, HE1, WS1);

    {
        const float* b1p = bias + 384;
        #pragma unroll
        for (int i = 0; i < 2; i++) {
            int r0 = wm * 32 + i * 16 + (lane >> 2);
            #pragma unroll
            for (int j = 0; j < 4; j++) {
                int c = wn * 32 + j * 8 + (lane & 3) * 2;
                float2 bb = *(const float2*)(b1p + c);
                int eA = e0 + r0, eB = eA + 8;
                if (eA < E)
                    *(float2*)(new_edges + (size_t)eA * D + c) =
                        make_float2(leaky(acc[1][i][j][0] + bb.x), leaky(acc[1][i][j][1] + bb.y));
                if (eB < E)
                    *(float2*)(new_edges + (size_t)eB * D + c) =
                        make_float2(leaky(acc[1][i][j][2] + bb.x), leaky(acc[1][i][j][3] + bb.y));
            }
        }
    }
    asm volatile("cp.async.bulk.wait_group.read 0;" ::: "memory");
}

// ============================================================================
extern "C" void kernel_launch(void* const* d_in, const int* in_sizes, int n_in,
                              void* d_out, int out_size)
{
    const float* nodes     = (const float*)d_in[0];
    const float* edges     = (const float*)d_in[1];
    const float* globals_  = (const float*)d_in[2];
    const int*   senders   = (const int*)d_in[3];
    const int*   receivers = (const int*)d_in[4];

    const float* node_W0 = (const float*)d_in[7];
    const float* node_b0 = (const float*)d_in[8];
    const float* node_W1 = (const float*)d_in[9];
    const float* node_b1 = (const float*)d_in[10];
    const float* edge_W0 = (const float*)d_in[11];
    const float* edge_b0 = (const float*)d_in[12];
    const float* edge_W1 = (const float*)d_in[13];
    const float* edge_b1 = (const float*)d_in[14];
    const float* glob_W0 = (const float*)d_in[15];
    const float* glob_b0 = (const float*)d_in[16];
    const float* glob_W1 = (const float*)d_in[17];
    const float* glob_b1 = (const float*)d_in[18];
    const float* gnode_W0 = (const float*)d_in[19];
    const float* gnode_b0 = (const float*)d_in[20];
    const float* gnode_W1 = (const float*)d_in[21];
    const float* gnode_b1 = (const float*)d_in[22];
    const float* gedge_W0 = (const float*)d_in[23];
    const float* gedge_b0 = (const float*)d_in[24];
    const float* gedge_W1 = (const float*)d_in[25];
    const float* gedge_b1 = (const float*)d_in[26];
    const float* fin_W0 = (const float*)d_in[27];
    const float* fin_b0 = (const float*)d_in[28];
    const float* fin_W1 = (const float*)d_in[29];
    const float* fin_b1 = (const float*)d_in[30];

    const int N = in_sizes[0] / D;
    const int E = in_sizes[3];
    const int G = in_sizes[5];
    const int epg = E / G;
    const int npg = N / G;

    float* new_nodes  = (float*)d_out;
    float* new_edges  = new_nodes + (size_t)N * D;
    float* new_global = new_edges + (size_t)E * D;

    // [0] fused init: zero targets + weight prep
    int n4 = N * D / 4;
    init_kernel<<<(n4 + 255) / 256, 256>>>(node_W0, node_W1, edge_W0, edge_W1,
                                           (float4*)new_nodes, n4);

    // [1] precompute per-node layer-1 partials + per-graph node sums
    cudaFuncSetAttribute(precompute_u_kernel,
                         cudaFuncAttributeMaxDynamicSharedMemorySize, P_SMEM);
    precompute_u_kernel<<<(N + 127) / 128, 512, P_SMEM>>>(nodes, N, npg);

    // [2] main edge kernel (also accumulates g_esum)
    cudaFuncSetAttribute(edge_mma_kernel,
                         cudaFuncAttributeMaxDynamicSharedMemorySize, E_SMEM);
    int grid = (E + 63) / 64;
    edge_mma_kernel<<<grid, 256, E_SMEM>>>(
        edges, senders, receivers,
        node_b0, node_b1, edge_b0, edge_b1,
        new_nodes, new_edges, E, epg);

    // [3] global branch MLPs (needs g_esum/g_nsum)
    dim3 gb(G, 3);
    global_branch_kernel<<<gb, 256>>>(globals_,
        glob_W0, glob_b0, glob_W1, glob_b1,
        gnode_W0, gnode_b0, gnode_W1, gnode_b1,
        gedge_W0, gedge_b0, gedge_W1, gedge_b1);

    // [4] final global MLP
    global_final_kernel<<<G, 256>>>(fin_W0, fin_b0, fin_W1, fin_b1, new_global);
}

// round 15
// speedup vs baseline: 1.0551x; 1.0367x over previous
#include <cuda_runtime.h>
#include <cuda_fp16.h>
#include <cstdint>

#define D 128
#define ROWSTRIDE 144
#define NMAX 51200

// ---- precompute kernel smem layout (2 A tiles + 2 W slots) ----
#define P_A0   0
#define P_A1   18432
#define P_W0   36864
#define P_SMEM 73728

// ---- edge kernel smem layout (2 CTAs/SM) ----
#define WS0   0                            // W slot 0 (128n x 64k, 18432B)
#define WS1   18432                        // W slot 1
#define A0T   36864                        // A/H tile c0 (64 x 144 = 9216)
#define A1T   46080                        // A/H tile c1
#define HE0   55296                        // H-edge c0
#define HE1   64512                        // H-edge c1
#define US0   73728                        // U staging br0 (64 x 272 = 17408)
#define US1   91136                        // U staging br1
#define STG   73728                        // node-out staging (64 x 528) reuses US
#define IDXO  108544                       // sidx[64], ridx[64]
#define BIASO 109056                       // 512 floats
#define E_SMEM 111104
#define USTRIDE 272
#define STAG_STRIDE 528

__device__ __forceinline__ uint32_t smem_u32(const void* p) {
    uint32_t a;
    asm("{ .reg .u64 t; cvta.to.shared.u64 t, %1; cvt.u32.u64 %0, t; }" : "=r"(a) : "l"(p));
    return a;
}
__device__ __forceinline__ float leaky(float x) { return x > 0.0f ? x : 0.01f * x; }
__device__ __forceinline__ uint32_t pack_f16(float a, float b) {
    __half2 t = __floats2half2_rn(a, b);
    return reinterpret_cast<uint32_t&>(t);
}
__device__ __forceinline__ __half2 u2h2(uint32_t u) { return reinterpret_cast<__half2&>(u); }
__device__ __forceinline__ uint32_t h22u(__half2 h) { return reinterpret_cast<uint32_t&>(h); }
__device__ __forceinline__ void ldsm_x4(uint32_t addr, uint32_t r[4]) {
    asm volatile("ldmatrix.sync.aligned.m8n8.x4.shared.b16 {%0,%1,%2,%3}, [%4];"
                 : "=r"(r[0]), "=r"(r[1]), "=r"(r[2]), "=r"(r[3]) : "r"(addr));
}
__device__ __forceinline__ void mma_f16(float* c, const uint32_t* a, uint32_t b0, uint32_t b1) {
    asm volatile("mma.sync.aligned.m16n8k16.row.col.f32.f16.f16.f32 "
                 "{%0,%1,%2,%3}, {%4,%5,%6,%7}, {%8,%9}, {%0,%1,%2,%3};"
                 : "+f"(c[0]), "+f"(c[1]), "+f"(c[2]), "+f"(c[3])
                 : "r"(a[0]), "r"(a[1]), "r"(a[2]), "r"(a[3]), "r"(b0), "r"(b1));
}
__device__ __forceinline__ void cp_async16(uint32_t saddr, const void* gaddr) {
    asm volatile("cp.async.cg.shared.global [%0], [%1], 16;" :: "r"(saddr), "l"(gaddr));
}
#define CP_COMMIT()  asm volatile("cp.async.commit_group;" ::: "memory")
#define CP_WAIT0()   asm volatile("cp.async.wait_group 0;" ::: "memory")
#define FENCE_PROXY_ASYNC() asm volatile("fence.proxy.async.shared::cta;" ::: "memory")

// ============================================================================
// Device scratch
// ============================================================================
__device__ __half g_W0T[2][128 * 384];   // [branch][n(out)][k] transposed fp16
__device__ __half g_W1T[2][128 * 128];
__device__ __half g_Us[NMAX * 256];      // per-node sender partials [n][br*128+c]
__device__ __half g_Ur[NMAX * 256];      // per-node receiver partials
__device__ float g_nsum[256 * 128];      // per-graph node sums
__device__ float g_esum[256 * 128];      // per-graph edge sums
__device__ float g_cat[256][384];        // concat of 3 global-branch MLPs

// ============================================================================
// [0] fused init: zero new_nodes + zero nsum/esum + weight prep
// ============================================================================
__global__ void init_kernel(const float* __restrict__ nW0, const float* __restrict__ nW1,
                            const float* __restrict__ eW0, const float* __restrict__ eW1,
                            float4* __restrict__ zp, int n4)
{
    int i = blockIdx.x * 256 + threadIdx.x;
    float4 z = make_float4(0.f, 0.f, 0.f, 0.f);
    if (i < n4) zp[i] = z;
    if (i < 8192) {
        ((float4*)g_esum)[i] = z;
        ((float4*)g_nsum)[i] = z;
    }
    if (i < 98304) {                      // W0T: 2 * 128*384
        int b = i / 49152, r = i % 49152;
        int n = r / 384, k = r % 384;
        g_W0T[b][n * 384 + k] = __float2half_rn((b ? eW0 : nW0)[k * 128 + n]);
    } else if (i < 131072) {              // W1T: 2 * 128*128
        int j = i - 98304;
        int b = j / 16384, r = j % 16384;
        int n = r / 128, k = r % 128;
        g_W1T[b][n * 128 + k] = __float2half_rn((b ? eW1 : nW1)[k * 128 + n]);
    }
}

// ============================================================================
// [1] precompute U_s / U_r + per-graph node sums: grid N/128, 512 thr, 2 CTAs/SM
// ============================================================================
__global__ __launch_bounds__(512, 2)
void precompute_u_kernel(const float* __restrict__ nodes, int N, int npg)
{
    extern __shared__ char smem[];
    const uint32_t sb = smem_u32(smem);
    const int tid = threadIdx.x;
    const int wid = tid >> 5;
    const int lane = tid & 31;
    const int wm = wid >> 2, wn = wid & 3;
    const int n0 = blockIdx.x * 128;

    // A: nodes rows -> fp16 tiles P_A0/P_A1
    {
        int row = tid >> 2;
        int nn = n0 + row; if (nn >= N) nn = N - 1;
        int cbase = (tid & 3) * 32;
        const float4* p4 = (const float4*)(nodes + (size_t)nn * D + cbase);
        float4 pf[8];
        #pragma unroll
        for (int i = 0; i < 8; i++) pf[i] = p4[i];
        #pragma unroll
        for (int i = 0; i < 8; i++) {
            float4 x = pf[i];
            int c = cbase + i * 4;
            char* A = smem + ((c >> 6) ? P_A1 : P_A0);
            *(uint2*)(A + row * ROWSTRIDE + (c & 63) * 2) =
                make_uint2(pack_f16(x.x, x.y), pack_f16(x.z, x.w));
        }
    }
    __syncthreads();

    // per-graph node column sums (from fp16 A tiles)
    {
        int col = tid & 127, grp = tid >> 7;
        const char* A = smem + ((col >> 6) ? P_A1 : P_A0);
        int cl = col & 63;
        int rbase = grp * 32;
        int gg = (n0 + rbase) / npg;
        int split = (gg + 1) * npg - (n0 + rbase);
        if (split > 32) split = 32;
        float s0 = 0.f, s1 = 0.f;
        #pragma unroll 8
        for (int r = 0; r < 32; r++) {
            int n = n0 + rbase + r;
            if (n < N) {
                float v = __half2float(*(const __half*)(A + (rbase + r) * ROWSTRIDE + cl * 2));
                if (r < split) s0 += v; else s1 += v;
            }
        }
        atomicAdd(&g_nsum[gg * 128 + col], s0);
        if (split < 32 && (n0 + rbase + split) < N)
            atomicAdd(&g_nsum[(gg + 1) * 128 + col], s1);
    }

    #pragma unroll 1
    for (int g = 0; g < 4; g++) {
        int tab = g >> 1, br = g & 1;

        #pragma unroll
        for (int u = 0; u < 4; u++) {
            int i = tid + u * 512;
            int t = i >> 10, r = i & 1023, n = r >> 3, q = r & 7;
            cp_async16(sb + P_W0 + t * 18432 + n * ROWSTRIDE + q * 16,
                       (const char*)g_W0T[br] + n * 768 + tab * 256 + t * 128 + q * 16);
        }
        CP_COMMIT();
        CP_WAIT0();
        __syncthreads();

        float acc[2][4][4];
        #pragma unroll
        for (int i = 0; i < 2; i++)
            #pragma unroll
            for (int j = 0; j < 4; j++)
                #pragma unroll
                for (int q = 0; q < 4; q++) acc[i][j][q] = 0.f;

        #pragma unroll
        for (int kc = 0; kc < 2; kc++) {
            uint32_t A = sb + (kc ? P_A1 : P_A0);
            uint32_t W = sb + P_W0 + kc * 18432;
            #pragma unroll
            for (int kk = 0; kk < 4; kk++) {
                uint32_t ah[2][4];
                #pragma unroll
                for (int i = 0; i < 2; i++) {
                    uint32_t off = (wm * 32 + i * 16 + (lane & 15)) * ROWSTRIDE
                                 + (lane >> 4) * 16 + kk * 32;
                    ldsm_x4(A + off, ah[i]);
                }
                uint32_t boffA = (wn * 32 + ((lane >> 4) * 8) + (lane & 7)) * ROWSTRIDE
                               + ((lane >> 3) & 1) * 16 + kk * 32;
                uint32_t bh[2][4];
                ldsm_x4(W + boffA, bh[0]);
                ldsm_x4(W + boffA + 16 * ROWSTRIDE, bh[1]);
                #pragma unroll
                for (int i = 0; i < 2; i++)
                    #pragma unroll
                    for (int j = 0; j < 4; j++)
                        mma_f16(acc[i][j], ah[i], bh[j >> 1][(j & 1) * 2], bh[j >> 1][(j & 1) * 2 + 1]);
            }
        }

        __half* U = tab ? g_Ur : g_Us;
        #pragma unroll
        for (int i = 0; i < 2; i++) {
            int r0 = wm * 32 + i * 16 + (lane >> 2);
            int nA = n0 + r0, nB = nA + 8;
            #pragma unroll
            for (int j = 0; j < 4; j++) {
                int c = wn * 32 + j * 8 + (lane & 3) * 2;
                if (nA < N)
                    *(uint32_t*)(U + (size_t)nA * 256 + br * 128 + c) =
                        pack_f16(acc[i][j][0], acc[i][j][1]);
                if (nB < N)
                    *(uint32_t*)(U + (size_t)nB * 256 + br * 128 + c) =
                        pack_f16(acc[i][j][2], acc[i][j][3]);
            }
        }
        __syncthreads();
    }
}

// ============================================================================
// [3] global branch MLPs: grid (G, 3), block 512 (k-split quarters) -> g_cat
// ============================================================================
__global__ void global_branch_kernel(const float* __restrict__ globals_,
                                     const float* gW0, const float* gb0, const float* gW1, const float* gb1,
                                     const float* nW0, const float* nb0, const float* nW1, const float* nb1,
                                     const float* eW0, const float* eb0, const float* eW1, const float* eb1)
{
    __shared__ float in[D];
    __shared__ float h[D];
    __shared__ float part[4][D];
    int g = blockIdx.x, b = blockIdx.y;
    int d = threadIdx.x & 127, quarter = threadIdx.x >> 7;
    int k0 = quarter * 32;

    const float *W0, *b0, *W1, *b1;
    if (b == 0)      { W0 = gW0; b0 = gb0; W1 = gW1; b1 = gb1;
                       if (!quarter) in[d] = globals_[(size_t)g * D + d]; }
    else if (b == 1) { W0 = nW0; b0 = nb0; W1 = nW1; b1 = nb1;
                       if (!quarter) in[d] = g_nsum[g * D + d]; }
    else             { W0 = eW0; b0 = eb0; W1 = eW1; b1 = eb1;
                       if (!quarter) in[d] = g_esum[g * D + d]; }
    __syncthreads();

    float a0 = 0.f, a1 = 0.f, a2 = 0.f, a3 = 0.f;
    #pragma unroll 4
    for (int k = k0; k < k0 + 32; k += 4) {
        a0 = fmaf(in[k],     __ldg(W0 + k * D + d),       a0);
        a1 = fmaf(in[k + 1], __ldg(W0 + (k + 1) * D + d), a1);
        a2 = fmaf(in[k + 2], __ldg(W0 + (k + 2) * D + d), a2);
        a3 = fmaf(in[k + 3], __ldg(W0 + (k + 3) * D + d), a3);
    }
    part[quarter][d] = (a0 + a1) + (a2 + a3);
    __syncthreads();
    if (!quarter)
        h[d] = leaky(part[0][d] + part[1][d] + part[2][d] + part[3][d] + __ldg(b0 + d));
    __syncthreads();

    a0 = a1 = a2 = a3 = 0.f;
    #pragma unroll 4
    for (int k = k0; k < k0 + 32; k += 4) {
        a0 = fmaf(h[k],     __ldg(W1 + k * D + d),       a0);
        a1 = fmaf(h[k + 1], __ldg(W1 + (k + 1) * D + d), a1);
        a2 = fmaf(h[k + 2], __ldg(W1 + (k + 2) * D + d), a2);
        a3 = fmaf(h[k + 3], __ldg(W1 + (k + 3) * D + d), a3);
    }
    part[quarter][d] = (a0 + a1) + (a2 + a3);
    __syncthreads();
    if (!quarter)
        g_cat[g][b * D + d] = leaky(part[0][d] + part[1][d] + part[2][d] + part[3][d] + __ldg(b1 + d));
}

// ============================================================================
// [4] final global MLP: grid G, block 512 (k-split quarters)
// ============================================================================
__global__ void global_final_kernel(const float* fW0, const float* fb0,
                                    const float* fW1, const float* fb1,
                                    float* __restrict__ out_global)
{
    __shared__ float cat[3 * D];
    __shared__ float h[D];
    __shared__ float part[4][D];
    int g = blockIdx.x;
    int d = threadIdx.x & 127, quarter = threadIdx.x >> 7;

    if (!quarter) {
        cat[d]         = g_cat[g][d];
        cat[D + d]     = g_cat[g][D + d];
        cat[2 * D + d] = g_cat[g][2 * D + d];
    }
    __syncthreads();

    float a0 = 0.f, a1 = 0.f, a2 = 0.f, a3 = 0.f;
    int k0 = quarter * 96;
    #pragma unroll 4
    for (int k = k0; k < k0 + 96; k += 4) {
        a0 = fmaf(cat[k],     __ldg(fW0 + k * D + d),       a0);
        a1 = fmaf(cat[k + 1], __ldg(fW0 + (k + 1) * D + d), a1);
        a2 = fmaf(cat[k + 2], __ldg(fW0 + (k + 2) * D + d), a2);
        a3 = fmaf(cat[k + 3], __ldg(fW0 + (k + 3) * D + d), a3);
    }
    part[quarter][d] = (a0 + a1) + (a2 + a3);
    __syncthreads();
    if (!quarter)
        h[d] = leaky(part[0][d] + part[1][d] + part[2][d] + part[3][d] + __ldg(fb0 + d));
    __syncthreads();

    a0 = a1 = a2 = a3 = 0.f;
    int k1 = quarter * 32;
    #pragma unroll 4
    for (int k = k1; k < k1 + 32; k += 4) {
        a0 = fmaf(h[k],     __ldg(fW1 + k * D + d),       a0);
        a1 = fmaf(h[k + 1], __ldg(fW1 + (k + 1) * D + d), a1);
        a2 = fmaf(h[k + 2], __ldg(fW1 + (k + 2) * D + d), a2);
        a3 = fmaf(h[k + 3], __ldg(fW1 + (k + 3) * D + d), a3);
    }
    part[quarter][d] = (a0 + a1) + (a2 + a3);
    __syncthreads();
    if (!quarter)
        out_global[(size_t)g * D + d] = leaky(part[0][d] + part[1][d] + part[2][d] + part[3][d] + __ldg(fb1 + d));
}

// ============================================================================
// [2] main fused edge kernel: M=64 edges/CTA, 256 threads, 2 CTAs/SM.
// mma_l1: ALL 6 ldsm grouped per kk before MMAs (higher MLP / issue rate).
// ============================================================================
__global__ __launch_bounds__(256, 2)
void edge_mma_kernel(const float* __restrict__ edges,
                     const int*   __restrict__ senders,
                     const int*   __restrict__ receivers,
                     const float* __restrict__ nb0f, const float* __restrict__ nb1f,
                     const float* __restrict__ eb0f, const float* __restrict__ eb1f,
                     float* __restrict__ new_nodes,
                     float* __restrict__ new_edges,
                     int E, int epg)
{
    extern __shared__ char smem[];
    const uint32_t sb = smem_u32(smem);
    const int tid  = threadIdx.x;
    const int wid  = tid >> 5;
    const int lane = tid & 31;
    const int wm   = wid >> 2;   // 0..1 (M offset wm*32)
    const int wn   = wid & 3;    // 0..3 (N offset wn*32)
    const int e0   = blockIdx.x * 64;

    int*   sidx = (int*)(smem + IDXO);
    int*   ridx = (int*)(smem + IDXO + 256);
    float* bias = (float*)(smem + BIASO);

    // cp.async W0e chunk0 -> slots (br0 -> WS0, br1 -> WS1)
    #pragma unroll
    for (int u = 0; u < 8; u++) {
        int i = tid + u * 256;
        int t = i >> 10, r = i & 1023, n = r >> 3, q = r & 7;
        cp_async16(sb + t * 18432 + n * ROWSTRIDE + q * 16,
                   (const char*)g_W0T[t] + n * 768 + 512 + q * 16);
    }
    CP_COMMIT();

    if (tid < 64) {
        int ec = (e0 + tid < E) ? e0 + tid : E - 1;
        sidx[tid] = senders[ec];
        ridx[tid] = receivers[ec];
    }
    if (tid < 128) { bias[tid] = nb0f[tid]; bias[256 + tid] = eb0f[tid]; }
    else { int t = tid - 128; bias[128 + t] = nb1f[t]; bias[384 + t] = eb1f[t]; }

    // stage U branch-0 (indices straight from global; hides behind loads+L1 MMA)
    #pragma unroll
    for (int u = 0; u < 4; u++) {
        int i = tid + u * 256;
        int row = i >> 4, q = i & 15;
        int ec = (e0 + row < E) ? e0 + row : E - 1;
        int s = __ldg(senders + ec);
        int r = __ldg(receivers + ec);
        uint4 a = *(const uint4*)(g_Us + (size_t)s * 256 + q * 8);
        uint4 b = *(const uint4*)(g_Ur + (size_t)r * 256 + q * 8);
        uint4 o;
        o.x = h22u(__hadd2(u2h2(a.x), u2h2(b.x)));
        o.y = h22u(__hadd2(u2h2(a.y), u2h2(b.y)));
        o.z = h22u(__hadd2(u2h2(a.z), u2h2(b.z)));
        o.w = h22u(__hadd2(u2h2(a.w), u2h2(b.w)));
        *(uint4*)(smem + US0 + row * USTRIDE + q * 16) = o;
    }

    // A: edge rows (contiguous) -> fp16 tiles A0/A1
    {
        int row = tid >> 2;
        int ec = (e0 + row < E) ? e0 + row : E - 1;
        int cbase = (tid & 3) * 32;
        const float4* p4 = (const float4*)(edges + (size_t)ec * D + cbase);
        float4 pf[8];
        #pragma unroll
        for (int i = 0; i < 8; i++) pf[i] = p4[i];
        #pragma unroll
        for (int i = 0; i < 8; i++) {
            float4 x = pf[i];
            int c = cbase + i * 4;
            char* A = smem + ((c >> 6) ? A1T : A0T);
            *(uint2*)(A + row * ROWSTRIDE + (c & 63) * 2) =
                make_uint2(pack_f16(x.x, x.y), pack_f16(x.z, x.w));
        }
    }
    CP_WAIT0();
    __syncthreads();

    float acc[2][2][4][4];
    #pragma unroll
    for (int b = 0; b < 2; b++)
        #pragma unroll
        for (int i = 0; i < 2; i++)
            #pragma unroll
            for (int j = 0; j < 4; j++)
                #pragma unroll
                for (int q = 0; q < 4; q++) acc[b][i][j][q] = 0.f;

    // layer-1 MMA: one A tile, BOTH branches; all 6 ldsm grouped before MMAs
    auto mma_l1 = [&](uint32_t Aoff) {
        uint32_t A = sb + Aoff;
        #pragma unroll
        for (int kk = 0; kk < 4; kk++) {
            uint32_t ah[2][4];
            uint32_t bh[2][2][4];     // [branch][half]
            uint32_t aoff = (wm * 32 + (lane & 15)) * ROWSTRIDE
                          + (lane >> 4) * 16 + kk * 32;
            uint32_t boffA = (wn * 32 + ((lane >> 4) * 8) + (lane & 7)) * ROWSTRIDE
                           + ((lane >> 3) & 1) * 16 + kk * 32;
            ldsm_x4(A + aoff, ah[0]);
            ldsm_x4(A + aoff + 16 * ROWSTRIDE, ah[1]);
            ldsm_x4(sb + boffA, bh[0][0]);
            ldsm_x4(sb + boffA + 16 * ROWSTRIDE, bh[0][1]);
            ldsm_x4(sb + 18432 + boffA, bh[1][0]);
            ldsm_x4(sb + 18432 + boffA + 16 * ROWSTRIDE, bh[1][1]);
            #pragma unroll
            for (int br = 0; br < 2; br++)
                #pragma unroll
                for (int i = 0; i < 2; i++)
                    #pragma unroll
                    for (int j = 0; j < 4; j++)
                        mma_f16(acc[br][i][j], ah[i],
                                bh[br][j >> 1][(j & 1) * 2], bh[br][j >> 1][(j & 1) * 2 + 1]);
        }
    };
    // layer-2 MMA: one branch, one H tile, one W slot
    auto mma_l2 = [&](int br, uint32_t Hoff, uint32_t Woff) {
        uint32_t A = sb + Hoff;
        uint32_t W = sb + Woff;
        #pragma unroll
        for (int kk = 0; kk < 4; kk++) {
            uint32_t ah[2][4];
            uint32_t bh[2][4];
            uint32_t aoff = (wm * 32 + (lane & 15)) * ROWSTRIDE
                          + (lane >> 4) * 16 + kk * 32;
            uint32_t boffA = (wn * 32 + ((lane >> 4) * 8) + (lane & 7)) * ROWSTRIDE
                           + ((lane >> 3) & 1) * 16 + kk * 32;
            ldsm_x4(A + aoff, ah[0]);
            ldsm_x4(A + aoff + 16 * ROWSTRIDE, ah[1]);
            ldsm_x4(W + boffA, bh[0]);
            ldsm_x4(W + boffA + 16 * ROWSTRIDE, bh[1]);
            #pragma unroll
            for (int i = 0; i < 2; i++)
                #pragma unroll
                for (int j = 0; j < 4; j++)
                    mma_f16(acc[br][i][j], ah[i], bh[j >> 1][(j & 1) * 2], bh[j >> 1][(j & 1) * 2 + 1]);
        }
    };
    auto epilogue1 = [&](int br, uint32_t ustoff) {
        const char* ust = smem + ustoff;
        const int chunk = wn >> 1;
        char* Hh = smem + (br ? (chunk ? HE1 : HE0) : (chunk ? A1T : A0T));
        const float* b0p = bias + br * 256;
        #pragma unroll
        for (int i = 0; i < 2; i++) {
            int r0 = wm * 32 + i * 16 + (lane >> 2);
            int r1 = r0 + 8;
            #pragma unroll
            for (int j = 0; j < 4; j++) {
                int c  = wn * 32 + j * 8 + (lane & 3) * 2;
                int cl = c & 63;
                float2 bb = *(const float2*)(b0p + c);
                float2 fA = __half22float2(*(const __half2*)(ust + r0 * USTRIDE + c * 2));
                float2 fB = __half22float2(*(const __half2*)(ust + r1 * USTRIDE + c * 2));
                float v0 = leaky(acc[br][i][j][0] + fA.x + bb.x);
                float v1 = leaky(acc[br][i][j][1] + fA.y + bb.y);
                float v2 = leaky(acc[br][i][j][2] + fB.x + bb.x);
                float v3 = leaky(acc[br][i][j][3] + fB.y + bb.y);
                *(uint32_t*)(Hh + r0 * ROWSTRIDE + cl * 2) = pack_f16(v0, v1);
                *(uint32_t*)(Hh + r1 * ROWSTRIDE + cl * 2) = pack_f16(v2, v3);
            }
        }
    };

    // ---- layer 1 chunk 0 (A0 x W0e-c0, both branches) ----------------------
    mma_l1(A0T);
    __syncthreads();                          // W slots free

    // ---- reload W0e chunk1; meanwhile esum (scalar) + stage UST1 -----------
    #pragma unroll
    for (int u = 0; u < 8; u++) {
        int i = tid + u * 256;
        int t = i >> 10, r = i & 1023, n = r >> 3, q = r & 7;
        cp_async16(sb + t * 18432 + n * ROWSTRIDE + q * 16,
                   (const char*)g_W0T[t] + n * 768 + 640 + q * 16);
    }
    CP_COMMIT();
    {   // per-graph edge column sums (reads A0/A1)
        int col = tid & 127, grp = tid >> 7;   // grp 0..1, rows grp*32..+31
        const char* A = smem + ((col >> 6) ? A1T : A0T);
        int cl = col & 63;
        int rbase = grp * 32;
        int gg = (e0 + rbase) / epg;
        int split = (gg + 1) * epg - (e0 + rbase);
        if (split > 32) split = 32;
        float s0 = 0.f, s1 = 0.f;
        #pragma unroll 8
        for (int r = 0; r < 32; r++) {
            int e = e0 + rbase + r;
            if (e < E) {
                float v = __half2float(*(const __half*)(A + (rbase + r) * ROWSTRIDE + cl * 2));
                if (r < split) s0 += v; else s1 += v;
            }
        }
        atomicAdd(&g_esum[gg * 128 + col], s0);
        if (split < 32 && (e0 + rbase + split) < E)
            atomicAdd(&g_esum[(gg + 1) * 128 + col], s1);
    }
    #pragma unroll
    for (int u = 0; u < 4; u++) {
        int i = tid + u * 256;
        int row = i >> 4, q = i & 15;
        uint4 a = *(const uint4*)(g_Us + (size_t)sidx[row] * 256 + 128 + q * 8);
        uint4 b = *(const uint4*)(g_Ur + (size_t)ridx[row] * 256 + 128 + q * 8);
        uint4 o;
        o.x = h22u(__hadd2(u2h2(a.x), u2h2(b.x)));
        o.y = h22u(__hadd2(u2h2(a.y), u2h2(b.y)));
        o.z = h22u(__hadd2(u2h2(a.z), u2h2(b.z)));
        o.w = h22u(__hadd2(u2h2(a.w), u2h2(b.w)));
        *(uint4*)(smem + US1 + row * USTRIDE + q * 16) = o;
    }
    CP_WAIT0();
    __syncthreads();

    // ---- layer 1 chunk 1 (A1 x W0e-c1) -------------------------------------
    mma_l1(A1T);
    __syncthreads();

    // ---- reload W1n (c0 -> WS0, c1 -> WS1); epilogues write H --------------
    #pragma unroll
    for (int u = 0; u < 8; u++) {
        int i = tid + u * 256;
        int t = i >> 10, r = i & 1023, n = r >> 3, q = r & 7;
        cp_async16(sb + t * 18432 + n * ROWSTRIDE + q * 16,
                   (const char*)g_W1T[0] + n * 256 + t * 128 + q * 16);
    }
    CP_COMMIT();
    epilogue1(0, US0);    // H-node -> A0/A1 (A consumed)
    epilogue1(1, US1);    // H-edge -> HE0/HE1
    CP_WAIT0();
    __syncthreads();

    // ---- layer 2 branch 0 (node messages) ----------------------------------
    #pragma unroll
    for (int i = 0; i < 2; i++)
        #pragma unroll
        for (int j = 0; j < 4; j++)
            #pragma unroll
            for (int q = 0; q < 4; q++) acc[0][i][j][q] = 0.f;
    mma_l2(0, A0T, WS0);
    mma_l2(0, A1T, WS1);
    __syncthreads();

    // ---- reload W1e; stage node-out into STG; scatter ----------------------
    #pragma unroll
    for (int u = 0; u < 8; u++) {
        int i = tid + u * 256;
        int t = i >> 10, r = i & 1023, n = r >> 3, q = r & 7;
        cp_async16(sb + t * 18432 + n * ROWSTRIDE + q * 16,
                   (const char*)g_W1T[1] + n * 256 + t * 128 + q * 16);
    }
    CP_COMMIT();
    {
        char* stag = smem + STG;
        const float* b1p = bias + 128;
        #pragma unroll
        for (int i = 0; i < 2; i++) {
            int r0 = wm * 32 + i * 16 + (lane >> 2);
            #pragma unroll
            for (int j = 0; j < 4; j++) {
                int c = wn * 32 + j * 8 + (lane & 3) * 2;
                float2 bb = *(const float2*)(b1p + c);
                *(float2*)(stag + r0 * STAG_STRIDE + c * 4) =
                    make_float2(leaky(acc[0][i][j][0] + bb.x), leaky(acc[0][i][j][1] + bb.y));
                *(float2*)(stag + (r0 + 8) * STAG_STRIDE + c * 4) =
                    make_float2(leaky(acc[0][i][j][2] + bb.x), leaky(acc[0][i][j][3] + bb.y));
            }
        }
    }
    CP_WAIT0();
    __syncthreads();
    FENCE_PROXY_ASYNC();
    if (tid < 64 && (e0 + tid) < E) {
        const float* dst = new_nodes + (size_t)ridx[tid] * D;
        asm volatile("cp.reduce.async.bulk.global.shared::cta.bulk_group.add.f32 [%0], [%1], %2;"
                     :: "l"(dst), "r"(sb + STG + tid * STAG_STRIDE), "r"(512) : "memory");
    }
    asm volatile("cp.async.bulk.commit_group;" ::: "memory");

    // ---- layer 2 branch 1 (edge update) ------------------------------------
    #pragma unroll
    for (int i = 0; i < 2; i++)
        #pragma unroll
        for (int j = 0; j < 4; j++)
            #pragma unroll
            for (int q = 0; q < 4; q++) acc[1][i][j][q] = 0.f;
    mma_l2(1, HE0, WS0);
    mma_l2(1, HE1, WS1);

    {
        const float* b1p = bias + 384;
        #pragma unroll
        for (int i = 0; i < 2; i++) {
            int r0 = wm * 32 + i * 16 + (lane >> 2);
            #pragma unroll
            for (int j = 0; j < 4; j++) {
                int c = wn * 32 + j * 8 + (lane & 3) * 2;
                float2 bb = *(const float2*)(b1p + c);
                int eA = e0 + r0, eB = eA + 8;
                if (eA < E)
                    *(float2*)(new_edges + (size_t)eA * D + c) =
                        make_float2(leaky(acc[1][i][j][0] + bb.x), leaky(acc[1][i][j][1] + bb.y));
                if (eB < E)
                    *(float2*)(new_edges + (size_t)eB * D + c) =
                        make_float2(leaky(acc[1][i][j][2] + bb.x), leaky(acc[1][i][j][3] + bb.y));
            }
        }
    }
    asm volatile("cp.async.bulk.wait_group.read 0;" ::: "memory");
}

// ============================================================================
extern "C" void kernel_launch(void* const* d_in, const int* in_sizes, int n_in,
                              void* d_out, int out_size)
{
    const float* nodes     = (const float*)d_in[0];
    const float* edges     = (const float*)d_in[1];
    const float* globals_  = (const float*)d_in[2];
    const int*   senders   = (const int*)d_in[3];
    const int*   receivers = (const int*)d_in[4];

    const float* node_W0 = (const float*)d_in[7];
    const float* node_b0 = (const float*)d_in[8];
    const float* node_W1 = (const float*)d_in[9];
    const float* node_b1 = (const float*)d_in[10];
    const float* edge_W0 = (const float*)d_in[11];
    const float* edge_b0 = (const float*)d_in[12];
    const float* edge_W1 = (const float*)d_in[13];
    const float* edge_b1 = (const float*)d_in[14];
    const float* glob_W0 = (const float*)d_in[15];
    const float* glob_b0 = (const float*)d_in[16];
    const float* glob_W1 = (const float*)d_in[17];
    const float* glob_b1 = (const float*)d_in[18];
    const float* gnode_W0 = (const float*)d_in[19];
    const float* gnode_b0 = (const float*)d_in[20];
    const float* gnode_W1 = (const float*)d_in[21];
    const float* gnode_b1 = (const float*)d_in[22];
    const float* gedge_W0 = (const float*)d_in[23];
    const float* gedge_b0 = (const float*)d_in[24];
    const float* gedge_W1 = (const float*)d_in[25];
    const float* gedge_b1 = (const float*)d_in[26];
    const float* fin_W0 = (const float*)d_in[27];
    const float* fin_b0 = (const float*)d_in[28];
    const float* fin_W1 = (const float*)d_in[29];
    const float* fin_b1 = (const float*)d_in[30];

    const int N = in_sizes[0] / D;
    const int E = in_sizes[3];
    const int G = in_sizes[5];
    const int epg = E / G;
    const int npg = N / G;

    float* new_nodes  = (float*)d_out;
    float* new_edges  = new_nodes + (size_t)N * D;
    float* new_global = new_edges + (size_t)E * D;

    // [0] fused init: zero targets + weight prep
    int n4 = N * D / 4;
    init_kernel<<<(n4 + 255) / 256, 256>>>(node_W0, node_W1, edge_W0, edge_W1,
                                           (float4*)new_nodes, n4);

    // [1] precompute per-node layer-1 partials + per-graph node sums
    cudaFuncSetAttribute(precompute_u_kernel,
                         cudaFuncAttributeMaxDynamicSharedMemorySize, P_SMEM);
    precompute_u_kernel<<<(N + 127) / 128, 512, P_SMEM>>>(nodes, N, npg);

    // [2] main edge kernel (also accumulates g_esum)
    cudaFuncSetAttribute(edge_mma_kernel,
                         cudaFuncAttributeMaxDynamicSharedMemorySize, E_SMEM);
    int grid = (E + 63) / 64;
    edge_mma_kernel<<<grid, 256, E_SMEM>>>(
        edges, senders, receivers,
        node_b0, node_b1, edge_b0, edge_b1,
        new_nodes, new_edges, E, epg);

    // [3] global branch MLPs (needs g_esum/g_nsum)
    dim3 gb(G, 3);
    global_branch_kernel<<<gb, 512>>>(globals_,
        glob_W0, glob_b0, glob_W1, glob_b1,
        gnode_W0, gnode_b0, gnode_W1, gnode_b1,
        gedge_W0, gedge_b0, gedge_W1, gedge_b1);

    // [4] final global MLP
    global_final_kernel<<<G, 512>>>(fin_W0, fin_b0, fin_W1, fin_b1, new_global);
}